// round 14
// baseline (speedup 1.0000x reference)
#include <cuda_runtime.h>
#include <cuda_fp16.h>
#include <cstdint>

#define HN 128
#define FF 256
#define NMAX 50048
#define EMAX 800000
#define EPS 1e-5f
#define NBLK_N (NMAX / 64)    // 782
#define DEPTH 4

// ---------------- static scratch ----------------
__device__ float  g_P[(size_t)NMAX * FF];
__device__ float  g_agg[(size_t)NMAX * HN];
__device__ uint4  g_Ae[(size_t)(EMAX / 64) * 1024];   // edge A, fp16 frag-packed (written by pass1)
__device__ uint4  g_An[(size_t)NBLK_N * 1024];        // node A, fp16 frag-packed
__device__ uint2  g_Wt16[2][2][4096];                 // [mode][half] B fp16 frag-packed
__device__ uint2  g_Wt2[8192];                        // gate B, (filter,core)-interleaved
__device__ float  g_stats1[2 * FF];
__device__ float  g_stats2[2 * HN];
__device__ float  g_scale[FF];
__device__ float  g_shift[FF];
__device__ int    g_is64;

// ---------------- helpers ----------------
__device__ __forceinline__ uint32_t smem_u32(const void* p) {
    uint32_t a;
    asm("{ .reg .u64 t; cvta.to.shared.u64 t, %1; cvt.u32.u64 %0, t; }" : "=r"(a) : "l"(p));
    return a;
}
__device__ __forceinline__ float tanhf_(float x) {
    float t = __expf(2.f * x);
    return 1.f - __fdividef(2.f, t + 1.f);
}
__device__ __forceinline__ float tanha(float x) {
    float y; asm("tanh.approx.f32 %0, %1;" : "=f"(y) : "f"(x)); return y;
}
__device__ __forceinline__ float sigmoida(float x) {
    return fmaf(tanha(x * 0.5f), 0.5f, 0.5f);
}
__device__ __forceinline__ void mma16(float* c, const uint4 a, const uint2 b) {
    asm volatile("mma.sync.aligned.m16n8k16.row.col.f32.f16.f16.f32 "
                 "{%0,%1,%2,%3},{%4,%5,%6,%7},{%8,%9},{%0,%1,%2,%3};"
                 : "+f"(c[0]), "+f"(c[1]), "+f"(c[2]), "+f"(c[3])
                 : "r"(a.x), "r"(a.y), "r"(a.z), "r"(a.w), "r"(b.x), "r"(b.y));
}
__device__ __forceinline__ uint32_t h2u(__half2 h) {
    return *reinterpret_cast<uint32_t*>(&h);
}
__device__ __forceinline__ void cpasync16(uint32_t dst, const void* src) {
    asm volatile("cp.async.cg.shared.global [%0], [%1], 16;"
                 :: "r"(dst), "l"(src) : "memory");
}
#define CP_COMMIT() asm volatile("cp.async.commit_group;" ::: "memory")
__device__ __forceinline__ void cp_wait(int n) {
    if (n == 0)      asm volatile("cp.async.wait_group 0;" ::: "memory");
    else if (n == 1) asm volatile("cp.async.wait_group 1;" ::: "memory");
    else if (n == 2) asm volatile("cp.async.wait_group 2;" ::: "memory");
    else             asm volatile("cp.async.wait_group 3;" ::: "memory");
}
__device__ __forceinline__ void lds128(uint4& r, uint32_t addr) {
    asm volatile("ld.shared.v4.u32 {%0,%1,%2,%3}, [%4];"
                 : "=r"(r.x), "=r"(r.y), "=r"(r.z), "=r"(r.w) : "r"(addr));
}

// mma_gemm0 smem map (ring kernel, node GEMM)
#define ABUF_OFF  32768
#define SMEM_SZ   98304
// gemm_stats smem: B 32K | Astage 32K | sstat 1K
#define ST_A_OFF   32768
#define ST_SS_OFF  65536
#define SMEMS_SZ   66560
// gemm_gate smem: B2 64K | ss 2K | ring 8x4K
#define SS_OFF    65536
#define RING_OFF  67584
#define SMEM2_SZ  100352

// ---------------- small kernels ----------------
__global__ void detect_kernel(const unsigned* __restrict__ u) {
    unsigned v = 0;
    for (int k = threadIdx.x; k < 64; k += 32) v |= u[2 * k + 1];
#pragma unroll
    for (int o = 16; o; o >>= 1) v |= __shfl_xor_sync(0xffffffffu, v, o);
    if (threadIdx.x == 0) g_is64 = (v == 0) ? 1 : 0;
}

__global__ void zero_kernel(int aggCount) {
    const int stride = gridDim.x * blockDim.x;
    const int t0 = blockIdx.x * blockDim.x + threadIdx.x;
    for (int j = t0; j < aggCount; j += stride) g_agg[j] = 0.f;
    if (t0 < 2 * FF) g_stats1[t0] = 0.f;
    if (t0 < 2 * HN) g_stats2[t0] = 0.f;
}

// A pack (node only now)
__global__ void prepA_kernel(const float* __restrict__ A, uint4* __restrict__ dst,
                             int M, int nunits) {
    const int gid = blockIdx.x * blockDim.x + threadIdx.x;
    if (gid >= nunits) return;
    const int lane = gid & 31, mt = (gid >> 5) & 3, ks = (gid >> 7) & 7;
    const int block = gid >> 10;
    const int r0 = block * 64 + mt * 16 + (lane >> 2);
    const int r1 = r0 + 8;
    const int c0 = ks * 16 + (lane & 3) * 2;
    float2 v00 = make_float2(0.f, 0.f), v01 = v00, v10 = v00, v11 = v00;
    if (r0 < M) {
        v00 = *(const float2*)(A + (size_t)r0 * HN + c0);
        v01 = *(const float2*)(A + (size_t)r0 * HN + c0 + 8);
    }
    if (r1 < M) {
        v10 = *(const float2*)(A + (size_t)r1 * HN + c0);
        v11 = *(const float2*)(A + (size_t)r1 * HN + c0 + 8);
    }
    uint4 o;
    o.x = h2u(__floats2half2_rn(v00.x, v00.y));
    o.y = h2u(__floats2half2_rn(v10.x, v10.y));
    o.z = h2u(__floats2half2_rn(v01.x, v01.y));
    o.w = h2u(__floats2half2_rn(v11.x, v11.y));
    dst[gid] = o;
}

// B pack pass1/node
__global__ void prepW_kernel(const float* __restrict__ W1) {
    const int gid = blockIdx.x * blockDim.x + threadIdx.x;
    if (gid >= 16384) return;
    const int lane = gid & 31, nt = (gid >> 5) & 3, wn = (gid >> 7) & 3;
    const int ks = (gid >> 9) & 7, hf = (gid >> 12) & 1, mode = gid >> 13;
    const int n = hf * 128 + wn * 32 + nt * 8 + (lane >> 2);
    const int k = ks * 16 + (lane & 3) * 2 + mode * HN;
    uint2 o;
    o.x = h2u(__floats2half2_rn(W1[(size_t)k * FF + n], W1[(size_t)(k + 1) * FF + n]));
    o.y = h2u(__floats2half2_rn(W1[(size_t)(k + 8) * FF + n], W1[(size_t)(k + 9) * FF + n]));
    g_Wt16[mode][hf][gid & 4095] = o;
}

// B pack gate (R13)
__global__ void prepW2_kernel(const float* __restrict__ W1) {
    const int gid = blockIdx.x * blockDim.x + threadIdx.x;
    if (gid >= 8192) return;
    const int lane = gid & 31, g = (gid >> 5) & 31, ks = gid >> 10;
    const int pl = lane >> 2, j = pl >> 1, fc = pl & 1;
    const int nt = g & 7, wn = g >> 3;
    const int n = wn * 32 + j * 8 + nt + fc * 128;
    const int k = HN + ks * 16 + (lane & 3) * 2;
    uint2 o;
    o.x = h2u(__floats2half2_rn(W1[(size_t)k * FF + n], W1[(size_t)(k + 1) * FF + n]));
    o.y = h2u(__floats2half2_rn(W1[(size_t)(k + 8) * FF + n], W1[(size_t)(k + 9) * FF + n]));
    g_Wt2[gid] = o;
}

// ---------------- node GEMM (R13 MODE 0, ring) ----------------
__global__ __launch_bounds__(256, 2) void mma_gemm0(
    const uint4* __restrict__ Apk, const float* __restrict__ b1,
    float* __restrict__ outv, int M)
{
    extern __shared__ char smem[];
    uint2* Bs = (uint2*)smem;

    const int tid = threadIdx.x, lane = tid & 31, wid = tid >> 5;
    const int wm = wid & 1, wn = wid >> 1;
    const int ntiles = (M + 127) >> 7;
    const long long njobs = (long long)ntiles * 2;
    const int G = gridDim.x;
    const int halfc = blockIdx.x & 1;

    const uint32_t wbuf = smem_u32(smem) + ABUF_OFF + (uint32_t)wid * 8192
                          + (uint32_t)lane * 16;
    {
        const uint4* src = (const uint4*)&g_Wt16[0][halfc][0];
        uint4* dstv = (uint4*)Bs;
        for (int i = tid; i < 2048; i += 256) dstv[i] = src[i];
    }
    __syncthreads();

    float acc[4][4][4];
#pragma unroll
    for (int mt = 0; mt < 4; mt++)
#pragma unroll
        for (int nt = 0; nt < 4; nt++)
#pragma unroll
            for (int r = 0; r < 4; r++) acc[mt][nt][r] = 0.f;

    for (long long job = blockIdx.x; job < njobs; job += G) {
        const long long tile = job >> 1;
        const uint4* abase = Apk + ((tile * 2 + wm) << 10) + lane;

#pragma unroll
        for (int p = 0; p < DEPTH; p++) {
#pragma unroll
            for (int mt = 0; mt < 4; mt++)
                cpasync16(wbuf + (uint32_t)((p * 4 + mt) << 9),
                          abase + p * 128 + mt * 32);
            CP_COMMIT();
        }
#pragma unroll
        for (int ks = 0; ks < 8; ks++) {
            const int wn_ = (7 - ks < DEPTH - 1) ? (7 - ks) : (DEPTH - 1);
            cp_wait(wn_);
            uint2 bfr[4];
#pragma unroll
            for (int nt = 0; nt < 4; nt++)
                bfr[nt] = Bs[(ks * 16 + wn * 4 + nt) * 32 + lane];
            uint4 a[4];
#pragma unroll
            for (int mt = 0; mt < 4; mt++)
                lds128(a[mt], wbuf + (uint32_t)((((ks % DEPTH) * 4) + mt) << 9));
            if (ks + DEPTH < 8) {
#pragma unroll
                for (int mt = 0; mt < 4; mt++)
                    cpasync16(wbuf + (uint32_t)(((((ks + DEPTH) % DEPTH) * 4) + mt) << 9),
                              abase + (ks + DEPTH) * 128 + mt * 32);
                CP_COMMIT();
            }
#pragma unroll
            for (int mt = 0; mt < 4; mt++)
#pragma unroll
                for (int nt = 0; nt < 4; nt++)
                    mma16(acc[mt][nt], a[mt], bfr[nt]);
        }

        const long long rbase = tile << 7;
#pragma unroll
        for (int mt = 0; mt < 4; mt++) {
#pragma unroll
            for (int nt = 0; nt < 4; nt++) {
                const int c0 = halfc * 128 + wn * 32 + nt * 8 + 2 * (lane & 3);
#pragma unroll
                for (int h = 0; h < 2; h++) {
                    const long long row = rbase + wm * 64 + mt * 16 + (lane >> 2) + h * 8;
                    if (row < (long long)M) {
                        const float2 add = *(const float2*)(b1 + c0);
                        float2 o;
                        o.x = acc[mt][nt][2 * h] + add.x;
                        o.y = acc[mt][nt][2 * h + 1] + add.y;
                        *(float2*)(outv + row * FF + c0) = o;
                    }
                }
                acc[mt][nt][0] = 0.f; acc[mt][nt][1] = 0.f;
                acc[mt][nt][2] = 0.f; acc[mt][nt][3] = 0.f;
            }
        }
    }
}

// ---------------- pass1: staged A (raw fp32 -> frag smem + g_Ae) + BN1 stats ----
__global__ __launch_bounds__(256, 2) void gemm_stats(
    const float* __restrict__ Araw, const void* __restrict__ ibuf,
    uint4* __restrict__ Apk_out, int M)
{
    extern __shared__ char smem[];
    uint2* Bs = (uint2*)smem;
    uint4* As = (uint4*)(smem + ST_A_OFF);
    float* sstat = (float*)(smem + ST_SS_OFF);
    const uint32_t as_base = smem_u32(smem) + ST_A_OFF;

    const int tid = threadIdx.x, lane = tid & 31, wid = tid >> 5;
    const int wm = wid & 1, wn = wid >> 1;
    const int ntiles = (M + 127) >> 7;
    const long long njobs = (long long)ntiles * 2;
    const int G = gridDim.x;
    const int halfc = blockIdx.x & 1;
    const int is64 = g_is64;

    {
        const uint4* src = (const uint4*)&g_Wt16[1][halfc][0];
        uint4* dstv = (uint4*)Bs;
        for (int i = tid; i < 2048; i += 256) dstv[i] = src[i];
    }
    sstat[tid] = 0.f;
    __syncthreads();

    float acc[4][4][4];
#pragma unroll
    for (int mt = 0; mt < 4; mt++)
#pragma unroll
        for (int nt = 0; nt < 4; nt++)
#pragma unroll
            for (int r = 0; r < 4; r++) acc[mt][nt][r] = 0.f;

    bool first = true;
    for (long long job = blockIdx.x; job < njobs; job += G) {
        const long long tile = job >> 1;
        const long long rbase = tile << 7;

        // ---- stage: raw fp32 -> fp16 frag-packed smem (+ gmem from even CTAs) ----
        if (!first) __syncthreads();     // prior mainloop done reading As
        first = false;
#pragma unroll
        for (int u = 0; u < 8; u++) {
            const int g = u * 256 + tid;                  // 0..2047
            const int ln = g & 31, mtx = (g >> 5) & 3, ksx = (g >> 7) & 7;
            const int blk2 = g >> 10;
            const long long r0 = rbase + blk2 * 64 + mtx * 16 + (ln >> 2);
            const long long r1 = r0 + 8;
            const int c0 = ksx * 16 + (ln & 3) * 2;
            float2 v00 = make_float2(0.f, 0.f), v01 = v00, v10 = v00, v11 = v00;
            if (r0 < (long long)M) {
                v00 = *(const float2*)(Araw + r0 * HN + c0);
                v01 = *(const float2*)(Araw + r0 * HN + c0 + 8);
            }
            if (r1 < (long long)M) {
                v10 = *(const float2*)(Araw + r1 * HN + c0);
                v11 = *(const float2*)(Araw + r1 * HN + c0 + 8);
            }
            uint4 o;
            o.x = h2u(__floats2half2_rn(v00.x, v00.y));
            o.y = h2u(__floats2half2_rn(v10.x, v10.y));
            o.z = h2u(__floats2half2_rn(v01.x, v01.y));
            o.w = h2u(__floats2half2_rn(v11.x, v11.y));
            As[g] = o;
            if (halfc == 0) Apk_out[tile * 2048 + g] = o;
        }
        __syncthreads();

        // ---- mainloop from staged smem ----
        const uint32_t awarp = as_base + (uint32_t)(wm * 1024 + lane) * 16u;
#pragma unroll
        for (int ks = 0; ks < 8; ks++) {
            uint2 bfr[4];
#pragma unroll
            for (int nt = 0; nt < 4; nt++)
                bfr[nt] = Bs[(ks * 16 + wn * 4 + nt) * 32 + lane];
            uint4 a[4];
#pragma unroll
            for (int mt = 0; mt < 4; mt++)
                lds128(a[mt], awarp + (uint32_t)((ks * 4 + mt) << 9));
#pragma unroll
            for (int mt = 0; mt < 4; mt++)
#pragma unroll
                for (int nt = 0; nt < 4; nt++)
                    mma16(acc[mt][nt], a[mt], bfr[nt]);
        }

        // ---- stats epilogue ----
        float s[4][2], q[4][2];
#pragma unroll
        for (int nt = 0; nt < 4; nt++) {
            s[nt][0] = s[nt][1] = 0.f; q[nt][0] = q[nt][1] = 0.f;
        }
#pragma unroll
        for (int mt = 0; mt < 4; mt++) {
            long long pb[2]; bool valid[2];
#pragma unroll
            for (int h = 0; h < 2; h++) {
                const long long row = rbase + wm * 64 + mt * 16 + (lane >> 2) + h * 8;
                valid[h] = row < (long long)M;
                pb[h] = 0;
                if (valid[h]) {
                    const long long idx = is64 ? ((const long long*)ibuf)[row]
                                               : (long long)((const int*)ibuf)[row];
                    pb[h] = idx * FF;
                }
            }
#pragma unroll
            for (int nt = 0; nt < 4; nt++) {
                const int c0 = halfc * 128 + wn * 32 + nt * 8 + 2 * (lane & 3);
#pragma unroll
                for (int h = 0; h < 2; h++) {
                    if (!valid[h]) continue;
                    const float2 p = *(const float2*)(g_P + pb[h] + c0);
                    const float ox = acc[mt][nt][2 * h] + p.x;
                    const float oy = acc[mt][nt][2 * h + 1] + p.y;
                    s[nt][0] += ox; q[nt][0] = fmaf(ox, ox, q[nt][0]);
                    s[nt][1] += oy; q[nt][1] = fmaf(oy, oy, q[nt][1]);
                }
                acc[mt][nt][0] = 0.f; acc[mt][nt][1] = 0.f;
                acc[mt][nt][2] = 0.f; acc[mt][nt][3] = 0.f;
            }
        }
#pragma unroll
        for (int o = 4; o < 32; o <<= 1) {
#pragma unroll
            for (int nt = 0; nt < 4; nt++) {
                s[nt][0] += __shfl_xor_sync(0xffffffffu, s[nt][0], o);
                s[nt][1] += __shfl_xor_sync(0xffffffffu, s[nt][1], o);
                q[nt][0] += __shfl_xor_sync(0xffffffffu, q[nt][0], o);
                q[nt][1] += __shfl_xor_sync(0xffffffffu, q[nt][1], o);
            }
        }
        if (lane < 4) {
#pragma unroll
            for (int nt = 0; nt < 4; nt++) {
                const int lc = wn * 32 + nt * 8 + 2 * lane;
                atomicAdd(&sstat[lc], s[nt][0]);
                atomicAdd(&sstat[lc + 1], s[nt][1]);
                atomicAdd(&sstat[128 + lc], q[nt][0]);
                atomicAdd(&sstat[128 + lc + 1], q[nt][1]);
            }
        }
    }
    __syncthreads();
    if (tid < 128) {
        atomicAdd(&g_stats1[halfc * 128 + tid], sstat[tid]);
        atomicAdd(&g_stats1[256 + halfc * 128 + tid], sstat[128 + tid]);
    }
}

// ---------------- BN1 finalize ----------------
__global__ void finalize1_kernel(const float* __restrict__ gamma1,
                                 const float* __restrict__ beta1, float invE) {
    const int j = threadIdx.x;
    const float mu  = g_stats1[j] * invE;
    const float var = g_stats1[FF + j] * invE - mu * mu;
    const float s   = gamma1[j] * rsqrtf(var + EPS);
    g_scale[j] = s;
    g_shift[j] = beta1[j] - mu * s;
}

// ---------------- pass2: GEMM + gate + scatter (R13, unchanged) ----------------
__global__ __launch_bounds__(256, 2) void gemm_gate(
    const uint4* __restrict__ Apk, const void* __restrict__ ibuf, int E)
{
    extern __shared__ char smem[];
    uint2* B2s = (uint2*)smem;
    float* ss = (float*)(smem + SS_OFF);

    const int tid = threadIdx.x, lane = tid & 31, wid = tid >> 5;
    const int wm = wid & 1, wn = wid >> 1;
    const int nblk = (E + 63) >> 6;
    const int G = gridDim.x;
    const int is64 = g_is64;

    {
        const uint4* src = (const uint4*)&g_Wt2[0];
        uint4* dstv = (uint4*)B2s;
        for (int i = tid; i < 4096; i += 256) dstv[i] = src[i];
    }
    ss[tid] = g_scale[tid];
    ss[256 + tid] = g_shift[tid];
    __syncthreads();

    const uint32_t wbuf = smem_u32(smem) + RING_OFF + (uint32_t)wid * 4096
                          + (uint32_t)lane * 16;
    const int kbase = wn * 32 + (lane & 3) * 8;

    float acc[2][8][4];
#pragma unroll
    for (int mt = 0; mt < 2; mt++)
#pragma unroll
        for (int nt = 0; nt < 8; nt++)
#pragma unroll
            for (int r = 0; r < 4; r++) acc[mt][nt][r] = 0.f;

    for (int job = blockIdx.x; job < nblk; job += G) {
        const uint4* abase = Apk + ((long long)job << 10) + lane;

#pragma unroll
        for (int p = 0; p < DEPTH; p++) {
#pragma unroll
            for (int mt = 0; mt < 2; mt++)
                cpasync16(wbuf + (uint32_t)((p * 2 + mt) << 9),
                          abase + (p * 4 + wm * 2 + mt) * 32);
            CP_COMMIT();
        }
#pragma unroll
        for (int ks = 0; ks < 8; ks++) {
            const int wn_ = (7 - ks < DEPTH - 1) ? (7 - ks) : (DEPTH - 1);
            cp_wait(wn_);
            uint2 bfr[8];
#pragma unroll
            for (int nt = 0; nt < 8; nt++)
                bfr[nt] = B2s[(ks * 32 + wn * 8 + nt) * 32 + lane];
            uint4 a[2];
#pragma unroll
            for (int mt = 0; mt < 2; mt++)
                lds128(a[mt], wbuf + (uint32_t)((((ks % DEPTH) * 2) + mt) << 9));
            if (ks + DEPTH < 8) {
#pragma unroll
                for (int mt = 0; mt < 2; mt++)
                    cpasync16(wbuf + (uint32_t)(((((ks + DEPTH) % DEPTH) * 2) + mt) << 9),
                              abase + ((ks + DEPTH) * 4 + wm * 2 + mt) * 32);
                CP_COMMIT();
            }
#pragma unroll
            for (int mt = 0; mt < 2; mt++)
#pragma unroll
                for (int nt = 0; nt < 8; nt++)
                    mma16(acc[mt][nt], a[mt], bfr[nt]);
        }

#pragma unroll
        for (int mt = 0; mt < 2; mt++) {
#pragma unroll
            for (int h = 0; h < 2; h++) {
                const long long row = (long long)job * 64 + wm * 32 + mt * 16
                                      + (lane >> 2) + h * 8;
                if (row < (long long)E) {
                    const long long idx = is64 ? ((const long long*)ibuf)[row]
                                               : (long long)((const int*)ibuf)[row];
                    const float* prow = g_P + idx * FF;
                    const float4 pf0 = *(const float4*)(prow + kbase);
                    const float4 pf1 = *(const float4*)(prow + kbase + 4);
                    const float4 pc0 = *(const float4*)(prow + 128 + kbase);
                    const float4 pc1 = *(const float4*)(prow + 128 + kbase + 4);
                    const float pf[8] = {pf0.x, pf0.y, pf0.z, pf0.w,
                                         pf1.x, pf1.y, pf1.z, pf1.w};
                    const float pc[8] = {pc0.x, pc0.y, pc0.z, pc0.w,
                                         pc1.x, pc1.y, pc1.z, pc1.w};
                    float m[8];
#pragma unroll
                    for (int nt = 0; nt < 8; nt++) {
                        const int k = kbase + nt;
                        const float hF = acc[mt][nt][2 * h] + pf[nt];
                        const float hC = acc[mt][nt][2 * h + 1] + pc[nt];
                        m[nt] = sigmoida(hF * ss[k] + ss[256 + k])
                              * tanha(hC * ss[128 + k] + ss[384 + k]);
                    }
                    float* dst = g_agg + idx * HN + kbase;
                    asm volatile("red.global.add.v4.f32 [%0], {%1, %2, %3, %4};"
                                 :: "l"(dst), "f"(m[0]), "f"(m[1]), "f"(m[2]), "f"(m[3]) : "memory");
                    asm volatile("red.global.add.v4.f32 [%0], {%1, %2, %3, %4};"
                                 :: "l"(dst + 4), "f"(m[4]), "f"(m[5]), "f"(m[6]), "f"(m[7]) : "memory");
                }
            }
#pragma unroll
            for (int nt = 0; nt < 8; nt++) {
                acc[mt][nt][0] = 0.f; acc[mt][nt][1] = 0.f;
                acc[mt][nt][2] = 0.f; acc[mt][nt][3] = 0.f;
            }
        }
    }
}

// ---------------- BN2 + final ----------------
__global__ void stats2_kernel(int N) {
    const int t = blockIdx.x * blockDim.x + threadIdx.x;
    const int col = t & (HN - 1);
    const int r0 = t >> 7;
    const int rs = (gridDim.x * blockDim.x) >> 7;
    float s = 0.f, sq = 0.f;
    for (long long r = r0; r < N; r += rs) {
        const float v = g_agg[r * HN + col];
        s += v; sq = fmaf(v, v, sq);
    }
    atomicAdd(&g_stats2[col], s);
    atomicAdd(&g_stats2[HN + col], sq);
}

__global__ void final_kernel(const float* __restrict__ node_emb,
                             const float* __restrict__ gamma2,
                             const float* __restrict__ beta2,
                             float* __restrict__ out, int total, float invN) {
    const int t = blockIdx.x * blockDim.x + threadIdx.x;
    if (t >= total) return;
    const int col = t & (HN - 1);
    const float mu  = g_stats2[col] * invN;
    const float var = g_stats2[HN + col] * invN - mu * mu;
    const float c1  = (g_agg[t] - mu) * rsqrtf(var + EPS) * gamma2[col] + beta2[col];
    out[t] = tanhf_(node_emb[t] + c1);
}

// ---------------- launch ----------------
extern "C" void kernel_launch(void* const* d_in, const int* in_sizes, int n_in,
                              void* d_out, int out_size) {
    const float* node_emb = (const float*)d_in[0];
    const float* edge_emb = (const float*)d_in[1];
    const void*  ibuf     = d_in[2];
    const float* W1       = (const float*)d_in[3];
    const float* b1       = (const float*)d_in[4];
    const float* gamma1   = (const float*)d_in[5];
    const float* beta1    = (const float*)d_in[6];
    const float* gamma2   = (const float*)d_in[7];
    const float* beta2    = (const float*)d_in[8];
    float* out = (float*)d_out;

    const int N = in_sizes[0] / HN;
    const int E = in_sizes[1] / HN;

    static bool attr_done = false;
    if (!attr_done) {
        cudaFuncSetAttribute(mma_gemm0, cudaFuncAttributeMaxDynamicSharedMemorySize, SMEM_SZ);
        cudaFuncSetAttribute(gemm_stats, cudaFuncAttributeMaxDynamicSharedMemorySize, SMEMS_SZ);
        cudaFuncSetAttribute(gemm_gate, cudaFuncAttributeMaxDynamicSharedMemorySize, SMEM2_SZ);
        attr_done = true;
    }

    float*  g_P_ptr;  cudaGetSymbolAddress((void**)&g_P_ptr, g_P);
    uint4*  g_Ae_ptr; cudaGetSymbolAddress((void**)&g_Ae_ptr, g_Ae);
    uint4*  g_An_ptr; cudaGetSymbolAddress((void**)&g_An_ptr, g_An);

    detect_kernel<<<1, 32>>>((const unsigned*)ibuf);
    zero_kernel<<<4096, 256>>>(N * HN);
    prepW_kernel<<<64, 256>>>(W1);
    prepW2_kernel<<<32, 256>>>(W1);

    const int unitsN = NBLK_N * 1024;
    prepA_kernel<<<(unitsN + 255) / 256, 256>>>(node_emb, g_An_ptr, N, unitsN);

    mma_gemm0<<<296, 256, SMEM_SZ>>>(g_An_ptr, b1, g_P_ptr, N);
    gemm_stats<<<296, 256, SMEMS_SZ>>>(edge_emb, ibuf, g_Ae_ptr, E);

    finalize1_kernel<<<1, 256>>>(gamma1, beta1, 1.0f / (float)E);

    gemm_gate<<<296, 256, SMEM2_SZ>>>(g_Ae_ptr, ibuf, E);

    stats2_kernel<<<1024, 256>>>(N);
    final_kernel<<<(N * HN + 255) / 256, 256>>>(node_emb, gamma2, beta2, out,
                                                N * HN, 1.0f / (float)N);
}

// round 15
// speedup vs baseline: 1.1012x; 1.1012x over previous
#include <cuda_runtime.h>
#include <cuda_fp16.h>
#include <cstdint>

#define HN 128
#define FF 256
#define NMAX 50048
#define EMAX 800000
#define EPS 1e-5f
#define NBLK_N (NMAX / 64)    // 782
#define NBLK_E (EMAX / 64)    // 12500
#define DEPTH 4

// ---------------- static scratch ----------------
__device__ float  g_P[(size_t)NMAX * FF];
__device__ float  g_agg[(size_t)NMAX * HN];
__device__ uint4  g_Ae[(size_t)NBLK_E * 1024];   // edge A, fp16 frag-packed
__device__ uint4  g_An[(size_t)NBLK_N * 1024];   // node A, fp16 frag-packed
__device__ uint2  g_Wt16[2][2][4096];            // [mode][half] B fp16 frag-packed
__device__ uint2  g_Wt2[8192];                   // gate B, (filter,core)-interleaved
__device__ float  g_stats1[2 * FF];
__device__ float  g_stats2[2 * HN];
__device__ float  g_scale[FF];
__device__ float  g_shift[FF];
__device__ int    g_is64;

// ---------------- helpers ----------------
__device__ __forceinline__ uint32_t smem_u32(const void* p) {
    uint32_t a;
    asm("{ .reg .u64 t; cvta.to.shared.u64 t, %1; cvt.u32.u64 %0, t; }" : "=r"(a) : "l"(p));
    return a;
}
__device__ __forceinline__ float tanhf_(float x) {
    float t = __expf(2.f * x);
    return 1.f - __fdividef(2.f, t + 1.f);
}
__device__ __forceinline__ float tanha(float x) {
    float y; asm("tanh.approx.f32 %0, %1;" : "=f"(y) : "f"(x)); return y;
}
__device__ __forceinline__ float sigmoida(float x) {
    return fmaf(tanha(x * 0.5f), 0.5f, 0.5f);
}
__device__ __forceinline__ void mma16(float* c, const uint4 a, const uint2 b) {
    asm volatile("mma.sync.aligned.m16n8k16.row.col.f32.f16.f16.f32 "
                 "{%0,%1,%2,%3},{%4,%5,%6,%7},{%8,%9},{%0,%1,%2,%3};"
                 : "+f"(c[0]), "+f"(c[1]), "+f"(c[2]), "+f"(c[3])
                 : "r"(a.x), "r"(a.y), "r"(a.z), "r"(a.w), "r"(b.x), "r"(b.y));
}
__device__ __forceinline__ uint32_t h2u(__half2 h) {
    return *reinterpret_cast<uint32_t*>(&h);
}
__device__ __forceinline__ void cpasync16(uint32_t dst, const void* src) {
    asm volatile("cp.async.cg.shared.global [%0], [%1], 16;"
                 :: "r"(dst), "l"(src) : "memory");
}
#define CP_COMMIT() asm volatile("cp.async.commit_group;" ::: "memory")
__device__ __forceinline__ void cp_wait(int n) {
    if (n == 0)      asm volatile("cp.async.wait_group 0;" ::: "memory");
    else if (n == 1) asm volatile("cp.async.wait_group 1;" ::: "memory");
    else if (n == 2) asm volatile("cp.async.wait_group 2;" ::: "memory");
    else             asm volatile("cp.async.wait_group 3;" ::: "memory");
}
__device__ __forceinline__ void lds128(uint4& r, uint32_t addr) {
    asm volatile("ld.shared.v4.u32 {%0,%1,%2,%3}, [%4];"
                 : "=r"(r.x), "=r"(r.y), "=r"(r.z), "=r"(r.w) : "r"(addr));
}

// pass1 smem map
#define ABUF_OFF  32768
#define SSTAT_OFF 98304
#define SMEM_SZ   99328
// gate smem map: B2 64KB | ss 2KB | ring 8 warps x 4KB
#define SS_OFF    65536
#define RING_OFF  67584
#define SMEM2_SZ  100352

// ---------------- small kernels ----------------
__global__ void detect_kernel(const unsigned* __restrict__ u) {
    unsigned v = 0;
    for (int k = threadIdx.x; k < 64; k += 32) v |= u[2 * k + 1];
#pragma unroll
    for (int o = 16; o; o >>= 1) v |= __shfl_xor_sync(0xffffffffu, v, o);
    if (threadIdx.x == 0) g_is64 = (v == 0) ? 1 : 0;
}

__global__ void zero_kernel(int aggCount) {
    const int stride = gridDim.x * blockDim.x;
    const int t0 = blockIdx.x * blockDim.x + threadIdx.x;
    for (int j = t0; j < aggCount; j += stride) g_agg[j] = 0.f;
    if (t0 < 2 * FF) g_stats1[t0] = 0.f;
    if (t0 < 2 * HN) g_stats2[t0] = 0.f;
}

// A pack: 2 independent units per thread for MLP
__global__ void prepA_kernel(const float* __restrict__ A, uint4* __restrict__ dst,
                             int M, int nunits, int halfu) {
    const int gid0 = blockIdx.x * blockDim.x + threadIdx.x;
#pragma unroll
    for (int rep = 0; rep < 2; rep++) {
        const int gid = gid0 + rep * halfu;
        if (gid >= nunits) continue;
        const int lane = gid & 31, mt = (gid >> 5) & 3, ks = (gid >> 7) & 7;
        const int block = gid >> 10;
        const int r0 = block * 64 + mt * 16 + (lane >> 2);
        const int r1 = r0 + 8;
        const int c0 = ks * 16 + (lane & 3) * 2;
        float2 v00 = make_float2(0.f, 0.f), v01 = v00, v10 = v00, v11 = v00;
        if (r0 < M) {
            v00 = *(const float2*)(A + (size_t)r0 * HN + c0);
            v01 = *(const float2*)(A + (size_t)r0 * HN + c0 + 8);
        }
        if (r1 < M) {
            v10 = *(const float2*)(A + (size_t)r1 * HN + c0);
            v11 = *(const float2*)(A + (size_t)r1 * HN + c0 + 8);
        }
        uint4 o;
        o.x = h2u(__floats2half2_rn(v00.x, v00.y));
        o.y = h2u(__floats2half2_rn(v10.x, v10.y));
        o.z = h2u(__floats2half2_rn(v01.x, v01.y));
        o.w = h2u(__floats2half2_rn(v11.x, v11.y));
        dst[gid] = o;
    }
}

// B pack pass1/node
__global__ void prepW_kernel(const float* __restrict__ W1) {
    const int gid = blockIdx.x * blockDim.x + threadIdx.x;
    if (gid >= 16384) return;
    const int lane = gid & 31, nt = (gid >> 5) & 3, wn = (gid >> 7) & 3;
    const int ks = (gid >> 9) & 7, hf = (gid >> 12) & 1, mode = gid >> 13;
    const int n = hf * 128 + wn * 32 + nt * 8 + (lane >> 2);
    const int k = ks * 16 + (lane & 3) * 2 + mode * HN;
    uint2 o;
    o.x = h2u(__floats2half2_rn(W1[(size_t)k * FF + n], W1[(size_t)(k + 1) * FF + n]));
    o.y = h2u(__floats2half2_rn(W1[(size_t)(k + 8) * FF + n], W1[(size_t)(k + 9) * FF + n]));
    g_Wt16[mode][hf][gid & 4095] = o;
}

// B pack gate (filter,core)-interleaved
__global__ void prepW2_kernel(const float* __restrict__ W1) {
    const int gid = blockIdx.x * blockDim.x + threadIdx.x;
    if (gid >= 8192) return;
    const int lane = gid & 31, g = (gid >> 5) & 31, ks = gid >> 10;
    const int pl = lane >> 2, j = pl >> 1, fc = pl & 1;
    const int nt = g & 7, wn = g >> 3;
    const int n = wn * 32 + j * 8 + nt + fc * 128;
    const int k = HN + ks * 16 + (lane & 3) * 2;
    uint2 o;
    o.x = h2u(__floats2half2_rn(W1[(size_t)k * FF + n], W1[(size_t)(k + 1) * FF + n]));
    o.y = h2u(__floats2half2_rn(W1[(size_t)(k + 8) * FF + n], W1[(size_t)(k + 9) * FF + n]));
    g_Wt2[gid] = o;
}

// ---------------- pass1 GEMM (R13 + cross-job stats registers) ----------------
// MODE 0: g_P (fp32) = node_emb @ W_top + b1
// MODE 1: BN1 column stats of (edge_emb @ W_bot + g_P[i[row]]) -- no h store
template <int MODE>
__global__ __launch_bounds__(256, 2) void mma_gemm(
    const uint4* __restrict__ Apk, const float* __restrict__ b1,
    const void* __restrict__ ibuf, float* __restrict__ outv, int M)
{
    extern __shared__ char smem[];
    uint2* Bs = (uint2*)smem;
    float* sstat = (float*)(smem + SSTAT_OFF);

    const int tid = threadIdx.x, lane = tid & 31, wid = tid >> 5;
    const int wm = wid & 1, wn = wid >> 1;
    const int ntiles = (M + 127) >> 7;
    const long long njobs = (long long)ntiles * 2;
    const int G = gridDim.x;
    const int halfc = blockIdx.x & 1;
    const int is64 = (MODE == 1) ? g_is64 : 0;

    const uint32_t wbuf = smem_u32(smem) + ABUF_OFF + (uint32_t)wid * 8192
                          + (uint32_t)lane * 16;
    {
        const uint4* src = (const uint4*)&g_Wt16[MODE][halfc][0];
        uint4* dstv = (uint4*)Bs;
        for (int i = tid; i < 2048; i += 256) dstv[i] = src[i];
    }
    if (MODE == 1) sstat[tid] = 0.f;
    __syncthreads();

    float acc[4][4][4];
#pragma unroll
    for (int mt = 0; mt < 4; mt++)
#pragma unroll
        for (int nt = 0; nt < 4; nt++)
#pragma unroll
            for (int r = 0; r < 4; r++) acc[mt][nt][r] = 0.f;

    // cross-job stats accumulators (MODE 1)
    float s[4][2], q[4][2];
    if (MODE == 1) {
#pragma unroll
        for (int nt = 0; nt < 4; nt++) {
            s[nt][0] = s[nt][1] = 0.f; q[nt][0] = q[nt][1] = 0.f;
        }
    }

    for (long long job = blockIdx.x; job < njobs; job += G) {
        const long long tile = job >> 1;
        const uint4* abase = Apk + ((tile * 2 + wm) << 10) + lane;

#pragma unroll
        for (int p = 0; p < DEPTH; p++) {
#pragma unroll
            for (int mt = 0; mt < 4; mt++)
                cpasync16(wbuf + (uint32_t)((p * 4 + mt) << 9),
                          abase + p * 128 + mt * 32);
            CP_COMMIT();
        }
#pragma unroll
        for (int ks = 0; ks < 8; ks++) {
            const int wn_ = (7 - ks < DEPTH - 1) ? (7 - ks) : (DEPTH - 1);
            cp_wait(wn_);
            uint2 bfr[4];
#pragma unroll
            for (int nt = 0; nt < 4; nt++)
                bfr[nt] = Bs[(ks * 16 + wn * 4 + nt) * 32 + lane];
            uint4 a[4];
#pragma unroll
            for (int mt = 0; mt < 4; mt++)
                lds128(a[mt], wbuf + (uint32_t)((((ks % DEPTH) * 4) + mt) << 9));
            if (ks + DEPTH < 8) {
#pragma unroll
                for (int mt = 0; mt < 4; mt++)
                    cpasync16(wbuf + (uint32_t)(((((ks + DEPTH) % DEPTH) * 4) + mt) << 9),
                              abase + (ks + DEPTH) * 128 + mt * 32);
                CP_COMMIT();
            }
#pragma unroll
            for (int mt = 0; mt < 4; mt++)
#pragma unroll
                for (int nt = 0; nt < 4; nt++)
                    mma16(acc[mt][nt], a[mt], bfr[nt]);
        }

        // ---- epilogue ----
        const long long rbase = tile << 7;
#pragma unroll
        for (int mt = 0; mt < 4; mt++) {
            long long pb[2]; bool valid[2]; long long rown[2];
#pragma unroll
            for (int h = 0; h < 2; h++) {
                const long long row = rbase + wm * 64 + mt * 16 + (lane >> 2) + h * 8;
                rown[h] = row;
                valid[h] = row < (long long)M;
                pb[h] = 0;
                if (MODE == 1 && valid[h]) {
                    const long long idx = is64 ? ((const long long*)ibuf)[row]
                                               : (long long)((const int*)ibuf)[row];
                    pb[h] = idx * FF;
                }
            }
#pragma unroll
            for (int nt = 0; nt < 4; nt++) {
                const int c0 = halfc * 128 + wn * 32 + nt * 8 + 2 * (lane & 3);
#pragma unroll
                for (int h = 0; h < 2; h++) {
                    if (!valid[h]) continue;
                    if (MODE == 0) {
                        const float2 add = *(const float2*)(b1 + c0);
                        float2 o;
                        o.x = acc[mt][nt][2 * h] + add.x;
                        o.y = acc[mt][nt][2 * h + 1] + add.y;
                        *(float2*)(outv + rown[h] * FF + c0) = o;
                    } else {
                        const float2 p = *(const float2*)(g_P + pb[h] + c0);
                        const float ox = acc[mt][nt][2 * h] + p.x;
                        const float oy = acc[mt][nt][2 * h + 1] + p.y;
                        s[nt][0] += ox; q[nt][0] = fmaf(ox, ox, q[nt][0]);
                        s[nt][1] += oy; q[nt][1] = fmaf(oy, oy, q[nt][1]);
                    }
                }
                acc[mt][nt][0] = 0.f; acc[mt][nt][1] = 0.f;
                acc[mt][nt][2] = 0.f; acc[mt][nt][3] = 0.f;
            }
        }
    }

    // ---- single stats reduction at kernel end (MODE 1) ----
    if (MODE == 1) {
#pragma unroll
        for (int o = 4; o < 32; o <<= 1) {
#pragma unroll
            for (int nt = 0; nt < 4; nt++) {
                s[nt][0] += __shfl_xor_sync(0xffffffffu, s[nt][0], o);
                s[nt][1] += __shfl_xor_sync(0xffffffffu, s[nt][1], o);
                q[nt][0] += __shfl_xor_sync(0xffffffffu, q[nt][0], o);
                q[nt][1] += __shfl_xor_sync(0xffffffffu, q[nt][1], o);
            }
        }
        if (lane < 4) {
#pragma unroll
            for (int nt = 0; nt < 4; nt++) {
                const int lc = wn * 32 + nt * 8 + 2 * lane;
                atomicAdd(&sstat[lc], s[nt][0]);
                atomicAdd(&sstat[lc + 1], s[nt][1]);
                atomicAdd(&sstat[128 + lc], q[nt][0]);
                atomicAdd(&sstat[128 + lc + 1], q[nt][1]);
            }
        }
        __syncthreads();
        if (tid < 128) {
            atomicAdd(&g_stats1[halfc * 128 + tid], sstat[tid]);
            atomicAdd(&g_stats1[256 + halfc * 128 + tid], sstat[128 + tid]);
        }
    }
}

// ---------------- BN1 finalize ----------------
__global__ void finalize1_kernel(const float* __restrict__ gamma1,
                                 const float* __restrict__ beta1, float invE) {
    const int j = threadIdx.x;
    const float mu  = g_stats1[j] * invE;
    const float var = g_stats1[FF + j] * invE - mu * mu;
    const float s   = gamma1[j] * rsqrtf(var + EPS);
    g_scale[j] = s;
    g_shift[j] = beta1[j] - mu * s;
}

// ---------------- pass2: GEMM + gate + scatter (R13, unchanged) ----------------
__global__ __launch_bounds__(256, 2) void gemm_gate(
    const uint4* __restrict__ Apk, const void* __restrict__ ibuf, int E)
{
    extern __shared__ char smem[];
    uint2* B2s = (uint2*)smem;
    float* ss = (float*)(smem + SS_OFF);

    const int tid = threadIdx.x, lane = tid & 31, wid = tid >> 5;
    const int wm = wid & 1, wn = wid >> 1;
    const int nblk = (E + 63) >> 6;
    const int G = gridDim.x;
    const int is64 = g_is64;

    {
        const uint4* src = (const uint4*)&g_Wt2[0];
        uint4* dstv = (uint4*)B2s;
        for (int i = tid; i < 4096; i += 256) dstv[i] = src[i];
    }
    ss[tid] = g_scale[tid];
    ss[256 + tid] = g_shift[tid];
    __syncthreads();

    const uint32_t wbuf = smem_u32(smem) + RING_OFF + (uint32_t)wid * 4096
                          + (uint32_t)lane * 16;
    const int kbase = wn * 32 + (lane & 3) * 8;

    float acc[2][8][4];
#pragma unroll
    for (int mt = 0; mt < 2; mt++)
#pragma unroll
        for (int nt = 0; nt < 8; nt++)
#pragma unroll
            for (int r = 0; r < 4; r++) acc[mt][nt][r] = 0.f;

    for (int job = blockIdx.x; job < nblk; job += G) {
        const uint4* abase = Apk + ((long long)job << 10) + lane;

#pragma unroll
        for (int p = 0; p < DEPTH; p++) {
#pragma unroll
            for (int mt = 0; mt < 2; mt++)
                cpasync16(wbuf + (uint32_t)((p * 2 + mt) << 9),
                          abase + (p * 4 + wm * 2 + mt) * 32);
            CP_COMMIT();
        }
#pragma unroll
        for (int ks = 0; ks < 8; ks++) {
            const int wn_ = (7 - ks < DEPTH - 1) ? (7 - ks) : (DEPTH - 1);
            cp_wait(wn_);
            uint2 bfr[8];
#pragma unroll
            for (int nt = 0; nt < 8; nt++)
                bfr[nt] = B2s[(ks * 32 + wn * 8 + nt) * 32 + lane];
            uint4 a[2];
#pragma unroll
            for (int mt = 0; mt < 2; mt++)
                lds128(a[mt], wbuf + (uint32_t)((((ks % DEPTH) * 2) + mt) << 9));
            if (ks + DEPTH < 8) {
#pragma unroll
                for (int mt = 0; mt < 2; mt++)
                    cpasync16(wbuf + (uint32_t)(((((ks + DEPTH) % DEPTH) * 2) + mt) << 9),
                              abase + ((ks + DEPTH) * 4 + wm * 2 + mt) * 32);
                CP_COMMIT();
            }
#pragma unroll
            for (int mt = 0; mt < 2; mt++)
#pragma unroll
                for (int nt = 0; nt < 8; nt++)
                    mma16(acc[mt][nt], a[mt], bfr[nt]);
        }

#pragma unroll
        for (int mt = 0; mt < 2; mt++) {
#pragma unroll
            for (int h = 0; h < 2; h++) {
                const long long row = (long long)job * 64 + wm * 32 + mt * 16
                                      + (lane >> 2) + h * 8;
                if (row < (long long)E) {
                    const long long idx = is64 ? ((const long long*)ibuf)[row]
                                               : (long long)((const int*)ibuf)[row];
                    const float* prow = g_P + idx * FF;
                    const float4 pf0 = *(const float4*)(prow + kbase);
                    const float4 pf1 = *(const float4*)(prow + kbase + 4);
                    const float4 pc0 = *(const float4*)(prow + 128 + kbase);
                    const float4 pc1 = *(const float4*)(prow + 128 + kbase + 4);
                    const float pf[8] = {pf0.x, pf0.y, pf0.z, pf0.w,
                                         pf1.x, pf1.y, pf1.z, pf1.w};
                    const float pc[8] = {pc0.x, pc0.y, pc0.z, pc0.w,
                                         pc1.x, pc1.y, pc1.z, pc1.w};
                    float m[8];
#pragma unroll
                    for (int nt = 0; nt < 8; nt++) {
                        const int k = kbase + nt;
                        const float hF = acc[mt][nt][2 * h] + pf[nt];
                        const float hC = acc[mt][nt][2 * h + 1] + pc[nt];
                        m[nt] = sigmoida(hF * ss[k] + ss[256 + k])
                              * tanha(hC * ss[128 + k] + ss[384 + k]);
                    }
                    float* dst = g_agg + idx * HN + kbase;
                    asm volatile("red.global.add.v4.f32 [%0], {%1, %2, %3, %4};"
                                 :: "l"(dst), "f"(m[0]), "f"(m[1]), "f"(m[2]), "f"(m[3]) : "memory");
                    asm volatile("red.global.add.v4.f32 [%0], {%1, %2, %3, %4};"
                                 :: "l"(dst + 4), "f"(m[4]), "f"(m[5]), "f"(m[6]), "f"(m[7]) : "memory");
                }
            }
#pragma unroll
            for (int nt = 0; nt < 8; nt++) {
                acc[mt][nt][0] = 0.f; acc[mt][nt][1] = 0.f;
                acc[mt][nt][2] = 0.f; acc[mt][nt][3] = 0.f;
            }
        }
    }
}

// ---------------- BN2 + final ----------------
__global__ void stats2_kernel(int N) {
    const int t = blockIdx.x * blockDim.x + threadIdx.x;
    const int col = t & (HN - 1);
    const int r0 = t >> 7;
    const int rs = (gridDim.x * blockDim.x) >> 7;
    float s = 0.f, sq = 0.f;
    for (long long r = r0; r < N; r += rs) {
        const float v = g_agg[r * HN + col];
        s += v; sq = fmaf(v, v, sq);
    }
    atomicAdd(&g_stats2[col], s);
    atomicAdd(&g_stats2[HN + col], sq);
}

__global__ void final_kernel(const float* __restrict__ node_emb,
                             const float* __restrict__ gamma2,
                             const float* __restrict__ beta2,
                             float* __restrict__ out, int total, float invN) {
    const int t = blockIdx.x * blockDim.x + threadIdx.x;
    if (t >= total) return;
    const int col = t & (HN - 1);
    const float mu  = g_stats2[col] * invN;
    const float var = g_stats2[HN + col] * invN - mu * mu;
    const float c1  = (g_agg[t] - mu) * rsqrtf(var + EPS) * gamma2[col] + beta2[col];
    out[t] = tanhf_(node_emb[t] + c1);
}

// ---------------- launch ----------------
extern "C" void kernel_launch(void* const* d_in, const int* in_sizes, int n_in,
                              void* d_out, int out_size) {
    const float* node_emb = (const float*)d_in[0];
    const float* edge_emb = (const float*)d_in[1];
    const void*  ibuf     = d_in[2];
    const float* W1       = (const float*)d_in[3];
    const float* b1       = (const float*)d_in[4];
    const float* gamma1   = (const float*)d_in[5];
    const float* beta1    = (const float*)d_in[6];
    const float* gamma2   = (const float*)d_in[7];
    const float* beta2    = (const float*)d_in[8];
    float* out = (float*)d_out;

    const int N = in_sizes[0] / HN;
    const int E = in_sizes[1] / HN;

    static bool attr_done = false;
    if (!attr_done) {
        cudaFuncSetAttribute(mma_gemm<0>, cudaFuncAttributeMaxDynamicSharedMemorySize, SMEM_SZ);
        cudaFuncSetAttribute(mma_gemm<1>, cudaFuncAttributeMaxDynamicSharedMemorySize, SMEM_SZ);
        cudaFuncSetAttribute(gemm_gate, cudaFuncAttributeMaxDynamicSharedMemorySize, SMEM2_SZ);
        attr_done = true;
    }

    float*  g_P_ptr;  cudaGetSymbolAddress((void**)&g_P_ptr, g_P);
    uint4*  g_Ae_ptr; cudaGetSymbolAddress((void**)&g_Ae_ptr, g_Ae);
    uint4*  g_An_ptr; cudaGetSymbolAddress((void**)&g_An_ptr, g_An);

    detect_kernel<<<1, 32>>>((const unsigned*)ibuf);
    zero_kernel<<<4096, 256>>>(N * HN);
    prepW_kernel<<<64, 256>>>(W1);
    prepW2_kernel<<<32, 256>>>(W1);

    const int unitsN = NBLK_N * 1024;
    const int unitsE = NBLK_E * 1024;
    const int halfN = (unitsN + 1) / 2;
    const int halfE = (unitsE + 1) / 2;
    prepA_kernel<<<(halfN + 255) / 256, 256>>>(node_emb, g_An_ptr, N, unitsN, halfN);
    prepA_kernel<<<(halfE + 255) / 256, 256>>>(edge_emb, g_Ae_ptr, E, unitsE, halfE);

    mma_gemm<0><<<296, 256, SMEM_SZ>>>(g_An_ptr, b1, ibuf, g_P_ptr, N);
    mma_gemm<1><<<296, 256, SMEM_SZ>>>(g_Ae_ptr, b1, ibuf, nullptr, E);

    finalize1_kernel<<<1, 256>>>(gamma1, beta1, 1.0f / (float)E);

    gemm_gate<<<296, 256, SMEM2_SZ>>>(g_Ae_ptr, ibuf, E);

    stats2_kernel<<<1024, 256>>>(N);
    final_kernel<<<(N * HN + 255) / 256, 256>>>(node_emb, gamma2, beta2, out,
                                                N * HN, 1.0f / (float)N);
}

// round 16
// speedup vs baseline: 1.1462x; 1.0408x over previous
#include <cuda_runtime.h>
#include <cuda_fp16.h>
#include <cstdint>

#define HN 128
#define FF 256
#define NMAX 50048
#define EMAX 800000
#define EPS 1e-5f
#define NBLK_N (NMAX / 64)    // 782
#define NBLK_E (EMAX / 64)    // 12500
#define DEPTH 4

// ---------------- static scratch ----------------
__device__ __half g_P16[(size_t)NMAX * FF];      // P in fp16 (L2-resident, 25.6 MB)
__device__ float  g_agg[(size_t)NMAX * HN];
__device__ uint4  g_Ae[(size_t)NBLK_E * 1024];   // edge A, fp16 frag-packed
__device__ uint4  g_An[(size_t)NBLK_N * 1024];   // node A, fp16 frag-packed
__device__ uint2  g_Wt16[2][2][4096];            // [mode][half] B fp16 frag-packed
__device__ uint2  g_Wt2[8192];                   // gate B, (filter,core)-interleaved
__device__ float  g_stats1[2 * FF];
__device__ float  g_stats2[2 * HN];
__device__ float  g_scale[FF];
__device__ float  g_shift[FF];
__device__ int    g_is64;

// ---------------- helpers ----------------
__device__ __forceinline__ uint32_t smem_u32(const void* p) {
    uint32_t a;
    asm("{ .reg .u64 t; cvta.to.shared.u64 t, %1; cvt.u32.u64 %0, t; }" : "=r"(a) : "l"(p));
    return a;
}
__device__ __forceinline__ float tanhf_(float x) {
    float t = __expf(2.f * x);
    return 1.f - __fdividef(2.f, t + 1.f);
}
__device__ __forceinline__ float tanha(float x) {
    float y; asm("tanh.approx.f32 %0, %1;" : "=f"(y) : "f"(x)); return y;
}
__device__ __forceinline__ float sigmoida(float x) {
    return fmaf(tanha(x * 0.5f), 0.5f, 0.5f);
}
__device__ __forceinline__ void mma16(float* c, const uint4 a, const uint2 b) {
    asm volatile("mma.sync.aligned.m16n8k16.row.col.f32.f16.f16.f32 "
                 "{%0,%1,%2,%3},{%4,%5,%6,%7},{%8,%9},{%0,%1,%2,%3};"
                 : "+f"(c[0]), "+f"(c[1]), "+f"(c[2]), "+f"(c[3])
                 : "r"(a.x), "r"(a.y), "r"(a.z), "r"(a.w), "r"(b.x), "r"(b.y));
}
__device__ __forceinline__ uint32_t h2u(__half2 h) {
    return *reinterpret_cast<uint32_t*>(&h);
}
__device__ __forceinline__ void cpasync16(uint32_t dst, const void* src) {
    asm volatile("cp.async.cg.shared.global [%0], [%1], 16;"
                 :: "r"(dst), "l"(src) : "memory");
}
#define CP_COMMIT() asm volatile("cp.async.commit_group;" ::: "memory")
__device__ __forceinline__ void cp_wait(int n) {
    if (n == 0)      asm volatile("cp.async.wait_group 0;" ::: "memory");
    else if (n == 1) asm volatile("cp.async.wait_group 1;" ::: "memory");
    else if (n == 2) asm volatile("cp.async.wait_group 2;" ::: "memory");
    else             asm volatile("cp.async.wait_group 3;" ::: "memory");
}
__device__ __forceinline__ void lds128(uint4& r, uint32_t addr) {
    asm volatile("ld.shared.v4.u32 {%0,%1,%2,%3}, [%4];"
                 : "=r"(r.x), "=r"(r.y), "=r"(r.z), "=r"(r.w) : "r"(addr));
}

// pass1 smem map
#define ABUF_OFF  32768
#define SSTAT_OFF 98304
#define SMEM_SZ   99328
// gate smem map: B2 64KB | ss 2KB | ring 8 warps x 4KB
#define SS_OFF    65536
#define RING_OFF  67584
#define SMEM2_SZ  100352

// ---------------- small kernels ----------------
__global__ void detect_kernel(const unsigned* __restrict__ u) {
    unsigned v = 0;
    for (int k = threadIdx.x; k < 64; k += 32) v |= u[2 * k + 1];
#pragma unroll
    for (int o = 16; o; o >>= 1) v |= __shfl_xor_sync(0xffffffffu, v, o);
    if (threadIdx.x == 0) g_is64 = (v == 0) ? 1 : 0;
}

__global__ void zero_kernel(int aggCount) {
    const int stride = gridDim.x * blockDim.x;
    const int t0 = blockIdx.x * blockDim.x + threadIdx.x;
    for (int j = t0; j < aggCount; j += stride) g_agg[j] = 0.f;
    if (t0 < 2 * FF) g_stats1[t0] = 0.f;
    if (t0 < 2 * HN) g_stats2[t0] = 0.f;
}

// A pack: 2 independent units per thread for MLP
__global__ void prepA_kernel(const float* __restrict__ A, uint4* __restrict__ dst,
                             int M, int nunits, int halfu) {
    const int gid0 = blockIdx.x * blockDim.x + threadIdx.x;
#pragma unroll
    for (int rep = 0; rep < 2; rep++) {
        const int gid = gid0 + rep * halfu;
        if (gid >= nunits) continue;
        const int lane = gid & 31, mt = (gid >> 5) & 3, ks = (gid >> 7) & 7;
        const int block = gid >> 10;
        const int r0 = block * 64 + mt * 16 + (lane >> 2);
        const int r1 = r0 + 8;
        const int c0 = ks * 16 + (lane & 3) * 2;
        float2 v00 = make_float2(0.f, 0.f), v01 = v00, v10 = v00, v11 = v00;
        if (r0 < M) {
            v00 = *(const float2*)(A + (size_t)r0 * HN + c0);
            v01 = *(const float2*)(A + (size_t)r0 * HN + c0 + 8);
        }
        if (r1 < M) {
            v10 = *(const float2*)(A + (size_t)r1 * HN + c0);
            v11 = *(const float2*)(A + (size_t)r1 * HN + c0 + 8);
        }
        uint4 o;
        o.x = h2u(__floats2half2_rn(v00.x, v00.y));
        o.y = h2u(__floats2half2_rn(v10.x, v10.y));
        o.z = h2u(__floats2half2_rn(v01.x, v01.y));
        o.w = h2u(__floats2half2_rn(v11.x, v11.y));
        dst[gid] = o;
    }
}

// B pack pass1/node
__global__ void prepW_kernel(const float* __restrict__ W1) {
    const int gid = blockIdx.x * blockDim.x + threadIdx.x;
    if (gid >= 16384) return;
    const int lane = gid & 31, nt = (gid >> 5) & 3, wn = (gid >> 7) & 3;
    const int ks = (gid >> 9) & 7, hf = (gid >> 12) & 1, mode = gid >> 13;
    const int n = hf * 128 + wn * 32 + nt * 8 + (lane >> 2);
    const int k = ks * 16 + (lane & 3) * 2 + mode * HN;
    uint2 o;
    o.x = h2u(__floats2half2_rn(W1[(size_t)k * FF + n], W1[(size_t)(k + 1) * FF + n]));
    o.y = h2u(__floats2half2_rn(W1[(size_t)(k + 8) * FF + n], W1[(size_t)(k + 9) * FF + n]));
    g_Wt16[mode][hf][gid & 4095] = o;
}

// B pack gate (filter,core)-interleaved
__global__ void prepW2_kernel(const float* __restrict__ W1) {
    const int gid = blockIdx.x * blockDim.x + threadIdx.x;
    if (gid >= 8192) return;
    const int lane = gid & 31, g = (gid >> 5) & 31, ks = gid >> 10;
    const int pl = lane >> 2, j = pl >> 1, fc = pl & 1;
    const int nt = g & 7, wn = g >> 3;
    const int n = wn * 32 + j * 8 + nt + fc * 128;
    const int k = HN + ks * 16 + (lane & 3) * 2;
    uint2 o;
    o.x = h2u(__floats2half2_rn(W1[(size_t)k * FF + n], W1[(size_t)(k + 1) * FF + n]));
    o.y = h2u(__floats2half2_rn(W1[(size_t)(k + 8) * FF + n], W1[(size_t)(k + 9) * FF + n]));
    g_Wt2[gid] = o;
}

// ---------------- pass GEMMs (R15 + fp16 P) ----------------
// MODE 0: g_P16 (fp16) = node_emb @ W_top + b1
// MODE 1: BN1 column stats of (edge_emb @ W_bot + P16[i[row]])
template <int MODE>
__global__ __launch_bounds__(256, 2) void mma_gemm(
    const uint4* __restrict__ Apk, const float* __restrict__ b1,
    const void* __restrict__ ibuf, __half* __restrict__ outv, int M)
{
    extern __shared__ char smem[];
    uint2* Bs = (uint2*)smem;
    float* sstat = (float*)(smem + SSTAT_OFF);

    const int tid = threadIdx.x, lane = tid & 31, wid = tid >> 5;
    const int wm = wid & 1, wn = wid >> 1;
    const int ntiles = (M + 127) >> 7;
    const long long njobs = (long long)ntiles * 2;
    const int G = gridDim.x;
    const int halfc = blockIdx.x & 1;
    const int is64 = (MODE == 1) ? g_is64 : 0;

    const uint32_t wbuf = smem_u32(smem) + ABUF_OFF + (uint32_t)wid * 8192
                          + (uint32_t)lane * 16;
    {
        const uint4* src = (const uint4*)&g_Wt16[MODE][halfc][0];
        uint4* dstv = (uint4*)Bs;
        for (int i = tid; i < 2048; i += 256) dstv[i] = src[i];
    }
    if (MODE == 1) sstat[tid] = 0.f;
    __syncthreads();

    float acc[4][4][4];
#pragma unroll
    for (int mt = 0; mt < 4; mt++)
#pragma unroll
        for (int nt = 0; nt < 4; nt++)
#pragma unroll
            for (int r = 0; r < 4; r++) acc[mt][nt][r] = 0.f;

    float s[4][2], q[4][2];
    if (MODE == 1) {
#pragma unroll
        for (int nt = 0; nt < 4; nt++) {
            s[nt][0] = s[nt][1] = 0.f; q[nt][0] = q[nt][1] = 0.f;
        }
    }

    for (long long job = blockIdx.x; job < njobs; job += G) {
        const long long tile = job >> 1;
        const uint4* abase = Apk + ((tile * 2 + wm) << 10) + lane;

#pragma unroll
        for (int p = 0; p < DEPTH; p++) {
#pragma unroll
            for (int mt = 0; mt < 4; mt++)
                cpasync16(wbuf + (uint32_t)((p * 4 + mt) << 9),
                          abase + p * 128 + mt * 32);
            CP_COMMIT();
        }
#pragma unroll
        for (int ks = 0; ks < 8; ks++) {
            const int wn_ = (7 - ks < DEPTH - 1) ? (7 - ks) : (DEPTH - 1);
            cp_wait(wn_);
            uint2 bfr[4];
#pragma unroll
            for (int nt = 0; nt < 4; nt++)
                bfr[nt] = Bs[(ks * 16 + wn * 4 + nt) * 32 + lane];
            uint4 a[4];
#pragma unroll
            for (int mt = 0; mt < 4; mt++)
                lds128(a[mt], wbuf + (uint32_t)((((ks % DEPTH) * 4) + mt) << 9));
            if (ks + DEPTH < 8) {
#pragma unroll
                for (int mt = 0; mt < 4; mt++)
                    cpasync16(wbuf + (uint32_t)(((((ks + DEPTH) % DEPTH) * 4) + mt) << 9),
                              abase + (ks + DEPTH) * 128 + mt * 32);
                CP_COMMIT();
            }
#pragma unroll
            for (int mt = 0; mt < 4; mt++)
#pragma unroll
                for (int nt = 0; nt < 4; nt++)
                    mma16(acc[mt][nt], a[mt], bfr[nt]);
        }

        // ---- epilogue ----
        const long long rbase = tile << 7;
#pragma unroll
        for (int mt = 0; mt < 4; mt++) {
            long long pb[2]; bool valid[2]; long long rown[2];
#pragma unroll
            for (int h = 0; h < 2; h++) {
                const long long row = rbase + wm * 64 + mt * 16 + (lane >> 2) + h * 8;
                rown[h] = row;
                valid[h] = row < (long long)M;
                pb[h] = 0;
                if (MODE == 1 && valid[h]) {
                    const long long idx = is64 ? ((const long long*)ibuf)[row]
                                               : (long long)((const int*)ibuf)[row];
                    pb[h] = idx * FF;
                }
            }
#pragma unroll
            for (int nt = 0; nt < 4; nt++) {
                const int c0 = halfc * 128 + wn * 32 + nt * 8 + 2 * (lane & 3);
#pragma unroll
                for (int h = 0; h < 2; h++) {
                    if (!valid[h]) continue;
                    if (MODE == 0) {
                        const float2 add = *(const float2*)(b1 + c0);
                        *(__half2*)(outv + rown[h] * FF + c0) =
                            __floats2half2_rn(acc[mt][nt][2 * h] + add.x,
                                              acc[mt][nt][2 * h + 1] + add.y);
                    } else {
                        const float2 p = __half22float2(
                            *(const __half2*)(g_P16 + pb[h] + c0));
                        const float ox = acc[mt][nt][2 * h] + p.x;
                        const float oy = acc[mt][nt][2 * h + 1] + p.y;
                        s[nt][0] += ox; q[nt][0] = fmaf(ox, ox, q[nt][0]);
                        s[nt][1] += oy; q[nt][1] = fmaf(oy, oy, q[nt][1]);
                    }
                }
                acc[mt][nt][0] = 0.f; acc[mt][nt][1] = 0.f;
                acc[mt][nt][2] = 0.f; acc[mt][nt][3] = 0.f;
            }
        }
    }

    if (MODE == 1) {
#pragma unroll
        for (int o = 4; o < 32; o <<= 1) {
#pragma unroll
            for (int nt = 0; nt < 4; nt++) {
                s[nt][0] += __shfl_xor_sync(0xffffffffu, s[nt][0], o);
                s[nt][1] += __shfl_xor_sync(0xffffffffu, s[nt][1], o);
                q[nt][0] += __shfl_xor_sync(0xffffffffu, q[nt][0], o);
                q[nt][1] += __shfl_xor_sync(0xffffffffu, q[nt][1], o);
            }
        }
        if (lane < 4) {
#pragma unroll
            for (int nt = 0; nt < 4; nt++) {
                const int lc = wn * 32 + nt * 8 + 2 * lane;
                atomicAdd(&sstat[lc], s[nt][0]);
                atomicAdd(&sstat[lc + 1], s[nt][1]);
                atomicAdd(&sstat[128 + lc], q[nt][0]);
                atomicAdd(&sstat[128 + lc + 1], q[nt][1]);
            }
        }
        __syncthreads();
        if (tid < 128) {
            atomicAdd(&g_stats1[halfc * 128 + tid], sstat[tid]);
            atomicAdd(&g_stats1[256 + halfc * 128 + tid], sstat[128 + tid]);
        }
    }
}

// ---------------- BN1 finalize ----------------
__global__ void finalize1_kernel(const float* __restrict__ gamma1,
                                 const float* __restrict__ beta1, float invE) {
    const int j = threadIdx.x;
    const float mu  = g_stats1[j] * invE;
    const float var = g_stats1[FF + j] * invE - mu * mu;
    const float s   = gamma1[j] * rsqrtf(var + EPS);
    g_scale[j] = s;
    g_shift[j] = beta1[j] - mu * s;
}

// ---------------- pass2: GEMM + gate + scatter (fp16 P) ----------------
__global__ __launch_bounds__(256, 2) void gemm_gate(
    const uint4* __restrict__ Apk, const void* __restrict__ ibuf, int E)
{
    extern __shared__ char smem[];
    uint2* B2s = (uint2*)smem;
    float* ss = (float*)(smem + SS_OFF);

    const int tid = threadIdx.x, lane = tid & 31, wid = tid >> 5;
    const int wm = wid & 1, wn = wid >> 1;
    const int nblk = (E + 63) >> 6;
    const int G = gridDim.x;
    const int is64 = g_is64;

    {
        const uint4* src = (const uint4*)&g_Wt2[0];
        uint4* dstv = (uint4*)B2s;
        for (int i = tid; i < 4096; i += 256) dstv[i] = src[i];
    }
    ss[tid] = g_scale[tid];
    ss[256 + tid] = g_shift[tid];
    __syncthreads();

    const uint32_t wbuf = smem_u32(smem) + RING_OFF + (uint32_t)wid * 4096
                          + (uint32_t)lane * 16;
    const int kbase = wn * 32 + (lane & 3) * 8;

    float acc[2][8][4];
#pragma unroll
    for (int mt = 0; mt < 2; mt++)
#pragma unroll
        for (int nt = 0; nt < 8; nt++)
#pragma unroll
            for (int r = 0; r < 4; r++) acc[mt][nt][r] = 0.f;

    for (int job = blockIdx.x; job < nblk; job += G) {
        const uint4* abase = Apk + ((long long)job << 10) + lane;

#pragma unroll
        for (int p = 0; p < DEPTH; p++) {
#pragma unroll
            for (int mt = 0; mt < 2; mt++)
                cpasync16(wbuf + (uint32_t)((p * 2 + mt) << 9),
                          abase + (p * 4 + wm * 2 + mt) * 32);
            CP_COMMIT();
        }
#pragma unroll
        for (int ks = 0; ks < 8; ks++) {
            const int wn_ = (7 - ks < DEPTH - 1) ? (7 - ks) : (DEPTH - 1);
            cp_wait(wn_);
            uint2 bfr[8];
#pragma unroll
            for (int nt = 0; nt < 8; nt++)
                bfr[nt] = B2s[(ks * 32 + wn * 8 + nt) * 32 + lane];
            uint4 a[2];
#pragma unroll
            for (int mt = 0; mt < 2; mt++)
                lds128(a[mt], wbuf + (uint32_t)((((ks % DEPTH) * 2) + mt) << 9));
            if (ks + DEPTH < 8) {
#pragma unroll
                for (int mt = 0; mt < 2; mt++)
                    cpasync16(wbuf + (uint32_t)(((((ks + DEPTH) % DEPTH) * 2) + mt) << 9),
                              abase + ((ks + DEPTH) * 4 + wm * 2 + mt) * 32);
                CP_COMMIT();
            }
#pragma unroll
            for (int mt = 0; mt < 2; mt++)
#pragma unroll
                for (int nt = 0; nt < 8; nt++)
                    mma16(acc[mt][nt], a[mt], bfr[nt]);
        }

#pragma unroll
        for (int mt = 0; mt < 2; mt++) {
#pragma unroll
            for (int h = 0; h < 2; h++) {
                const long long row = (long long)job * 64 + wm * 32 + mt * 16
                                      + (lane >> 2) + h * 8;
                if (row < (long long)E) {
                    const long long idx = is64 ? ((const long long*)ibuf)[row]
                                               : (long long)((const int*)ibuf)[row];
                    const __half* prow = g_P16 + idx * FF;
                    const uint4 pfv = *(const uint4*)(prow + kbase);        // 8 halves
                    const uint4 pcv = *(const uint4*)(prow + 128 + kbase);  // 8 halves
                    float pf[8], pc[8];
#pragma unroll
                    for (int p2 = 0; p2 < 4; p2++) {
                        const float2 f2 = __half22float2(*(((const __half2*)&pfv) + p2));
                        const float2 c2 = __half22float2(*(((const __half2*)&pcv) + p2));
                        pf[2 * p2] = f2.x; pf[2 * p2 + 1] = f2.y;
                        pc[2 * p2] = c2.x; pc[2 * p2 + 1] = c2.y;
                    }
                    float m[8];
#pragma unroll
                    for (int nt = 0; nt < 8; nt++) {
                        const int k = kbase + nt;
                        const float hF = acc[mt][nt][2 * h] + pf[nt];
                        const float hC = acc[mt][nt][2 * h + 1] + pc[nt];
                        m[nt] = sigmoida(hF * ss[k] + ss[256 + k])
                              * tanha(hC * ss[128 + k] + ss[384 + k]);
                    }
                    float* dst = g_agg + idx * HN + kbase;
                    asm volatile("red.global.add.v4.f32 [%0], {%1, %2, %3, %4};"
                                 :: "l"(dst), "f"(m[0]), "f"(m[1]), "f"(m[2]), "f"(m[3]) : "memory");
                    asm volatile("red.global.add.v4.f32 [%0], {%1, %2, %3, %4};"
                                 :: "l"(dst + 4), "f"(m[4]), "f"(m[5]), "f"(m[6]), "f"(m[7]) : "memory");
                }
            }
#pragma unroll
            for (int nt = 0; nt < 8; nt++) {
                acc[mt][nt][0] = 0.f; acc[mt][nt][1] = 0.f;
                acc[mt][nt][2] = 0.f; acc[mt][nt][3] = 0.f;
            }
        }
    }
}

// ---------------- BN2 + final ----------------
__global__ void stats2_kernel(int N) {
    const int t = blockIdx.x * blockDim.x + threadIdx.x;
    const int col = t & (HN - 1);
    const int r0 = t >> 7;
    const int rs = (gridDim.x * blockDim.x) >> 7;
    float s = 0.f, sq = 0.f;
    for (long long r = r0; r < N; r += rs) {
        const float v = g_agg[r * HN + col];
        s += v; sq = fmaf(v, v, sq);
    }
    atomicAdd(&g_stats2[col], s);
    atomicAdd(&g_stats2[HN + col], sq);
}

__global__ void final_kernel(const float* __restrict__ node_emb,
                             const float* __restrict__ gamma2,
                             const float* __restrict__ beta2,
                             float* __restrict__ out, int total, float invN) {
    const int t = blockIdx.x * blockDim.x + threadIdx.x;
    if (t >= total) return;
    const int col = t & (HN - 1);
    const float mu  = g_stats2[col] * invN;
    const float var = g_stats2[HN + col] * invN - mu * mu;
    const float c1  = (g_agg[t] - mu) * rsqrtf(var + EPS) * gamma2[col] + beta2[col];
    out[t] = tanhf_(node_emb[t] + c1);
}

// ---------------- launch ----------------
extern "C" void kernel_launch(void* const* d_in, const int* in_sizes, int n_in,
                              void* d_out, int out_size) {
    const float* node_emb = (const float*)d_in[0];
    const float* edge_emb = (const float*)d_in[1];
    const void*  ibuf     = d_in[2];
    const float* W1       = (const float*)d_in[3];
    const float* b1       = (const float*)d_in[4];
    const float* gamma1   = (const float*)d_in[5];
    const float* beta1    = (const float*)d_in[6];
    const float* gamma2   = (const float*)d_in[7];
    const float* beta2    = (const float*)d_in[8];
    float* out = (float*)d_out;

    const int N = in_sizes[0] / HN;
    const int E = in_sizes[1] / HN;

    static bool attr_done = false;
    if (!attr_done) {
        cudaFuncSetAttribute(mma_gemm<0>, cudaFuncAttributeMaxDynamicSharedMemorySize, SMEM_SZ);
        cudaFuncSetAttribute(mma_gemm<1>, cudaFuncAttributeMaxDynamicSharedMemorySize, SMEM_SZ);
        cudaFuncSetAttribute(gemm_gate, cudaFuncAttributeMaxDynamicSharedMemorySize, SMEM2_SZ);
        attr_done = true;
    }

    __half* g_P_ptr;  cudaGetSymbolAddress((void**)&g_P_ptr, g_P16);
    uint4*  g_Ae_ptr; cudaGetSymbolAddress((void**)&g_Ae_ptr, g_Ae);
    uint4*  g_An_ptr; cudaGetSymbolAddress((void**)&g_An_ptr, g_An);

    detect_kernel<<<1, 32>>>((const unsigned*)ibuf);
    zero_kernel<<<4096, 256>>>(N * HN);
    prepW_kernel<<<64, 256>>>(W1);
    prepW2_kernel<<<32, 256>>>(W1);

    const int unitsN = NBLK_N * 1024;
    const int unitsE = NBLK_E * 1024;
    const int halfN = (unitsN + 1) / 2;
    const int halfE = (unitsE + 1) / 2;
    prepA_kernel<<<(halfN + 255) / 256, 256>>>(node_emb, g_An_ptr, N, unitsN, halfN);
    prepA_kernel<<<(halfE + 255) / 256, 256>>>(edge_emb, g_Ae_ptr, E, unitsE, halfE);

    mma_gemm<0><<<296, 256, SMEM_SZ>>>(g_An_ptr, b1, ibuf, g_P_ptr, N);
    mma_gemm<1><<<296, 256, SMEM_SZ>>>(g_Ae_ptr, b1, ibuf, nullptr, E);

    finalize1_kernel<<<1, 256>>>(gamma1, beta1, 1.0f / (float)E);

    gemm_gate<<<296, 256, SMEM2_SZ>>>(g_Ae_ptr, ibuf, E);

    stats2_kernel<<<1024, 256>>>(N);
    final_kernel<<<(N * HN + 255) / 256, 256>>>(node_emb, gamma2, beta2, out,
                                                N * HN, 1.0f / (float)N);
}

// round 17
// speedup vs baseline: 1.1505x; 1.0038x over previous
#include <cuda_runtime.h>
#include <cuda_fp16.h>
#include <cstdint>

#define HN 128
#define FF 256
#define NMAX 50048
#define EMAX 800000
#define EPS 1e-5f
#define NBLK_N (NMAX / 64)    // 782
#define NBLK_E (EMAX / 64)    // 12500
#define DEPTH 4

// ---------------- static scratch ----------------
__device__ __half g_P16[(size_t)NMAX * FF];      // P fp16 (L2-resident)
__device__ float  g_agg[(size_t)NMAX * HN];
__device__ uint4  g_Ae[(size_t)NBLK_E * 1024];
__device__ uint4  g_An[(size_t)NBLK_N * 1024];
__device__ uint2  g_Wt16[2][2][4096];
__device__ uint2  g_Wt2[8192];
__device__ float  g_stats1[2 * FF];
__device__ float  g_stats2[2 * HN];
__device__ int    g_is64;

// ---------------- helpers ----------------
__device__ __forceinline__ uint32_t smem_u32(const void* p) {
    uint32_t a;
    asm("{ .reg .u64 t; cvta.to.shared.u64 t, %1; cvt.u32.u64 %0, t; }" : "=r"(a) : "l"(p));
    return a;
}
__device__ __forceinline__ float tanhf_(float x) {
    float t = __expf(2.f * x);
    return 1.f - __fdividef(2.f, t + 1.f);
}
__device__ __forceinline__ float tanha(float x) {
    float y; asm("tanh.approx.f32 %0, %1;" : "=f"(y) : "f"(x)); return y;
}
__device__ __forceinline__ float sigmoida(float x) {
    return fmaf(tanha(x * 0.5f), 0.5f, 0.5f);
}
__device__ __forceinline__ void mma16(float* c, const uint4 a, const uint2 b) {
    asm volatile("mma.sync.aligned.m16n8k16.row.col.f32.f16.f16.f32 "
                 "{%0,%1,%2,%3},{%4,%5,%6,%7},{%8,%9},{%0,%1,%2,%3};"
                 : "+f"(c[0]), "+f"(c[1]), "+f"(c[2]), "+f"(c[3])
                 : "r"(a.x), "r"(a.y), "r"(a.z), "r"(a.w), "r"(b.x), "r"(b.y));
}
__device__ __forceinline__ uint32_t h2u(__half2 h) {
    return *reinterpret_cast<uint32_t*>(&h);
}
__device__ __forceinline__ void cpasync16(uint32_t dst, const void* src) {
    asm volatile("cp.async.cg.shared.global [%0], [%1], 16;"
                 :: "r"(dst), "l"(src) : "memory");
}
#define CP_COMMIT() asm volatile("cp.async.commit_group;" ::: "memory")
__device__ __forceinline__ void cp_wait(int n) {
    if (n == 0)      asm volatile("cp.async.wait_group 0;" ::: "memory");
    else if (n == 1) asm volatile("cp.async.wait_group 1;" ::: "memory");
    else if (n == 2) asm volatile("cp.async.wait_group 2;" ::: "memory");
    else             asm volatile("cp.async.wait_group 3;" ::: "memory");
}
__device__ __forceinline__ void lds128(uint4& r, uint32_t addr) {
    asm volatile("ld.shared.v4.u32 {%0,%1,%2,%3}, [%4];"
                 : "=r"(r.x), "=r"(r.y), "=r"(r.z), "=r"(r.w) : "r"(addr));
}

// pass1 smem map
#define ABUF_OFF  32768
#define SSTAT_OFF 98304
#define SMEM_SZ   99328
// gate smem map
#define SS_OFF    65536
#define RING_OFF  67584
#define SMEM2_SZ  100352

// ---------------- setup: detect + zeros + W packs, one launch ----------------
__global__ void setup_kernel(const unsigned* __restrict__ u,
                             const float* __restrict__ W1, int aggCount) {
    const int tid = threadIdx.x;
    const int b = blockIdx.x;

    // agg zero: all blocks stride over aggCount
    const int stride = gridDim.x * blockDim.x;
    for (int j = b * blockDim.x + tid; j < aggCount; j += stride) g_agg[j] = 0.f;

    if (b == 0) {
        // stats zeros
        g_stats1[tid] = 0.f; g_stats1[256 + tid] = 0.f;
        if (tid < 2 * HN) g_stats2[tid] = 0.f;
        // index dtype detect (warp 0)
        if (tid < 32) {
            unsigned v = 0;
            for (int k = tid; k < 64; k += 32) v |= u[2 * k + 1];
#pragma unroll
            for (int o = 16; o; o >>= 1) v |= __shfl_xor_sync(0xffffffffu, v, o);
            if (tid == 0) g_is64 = (v == 0) ? 1 : 0;
        }
    } else if (b >= 1 && b <= 64) {
        // prepW: pass1/node B packs
        const int gid = (b - 1) * 256 + tid;          // 0..16383
        const int lane = gid & 31, nt = (gid >> 5) & 3, wn = (gid >> 7) & 3;
        const int ks = (gid >> 9) & 7, hf = (gid >> 12) & 1, mode = gid >> 13;
        const int n = hf * 128 + wn * 32 + nt * 8 + (lane >> 2);
        const int k = ks * 16 + (lane & 3) * 2 + mode * HN;
        uint2 o;
        o.x = h2u(__floats2half2_rn(W1[(size_t)k * FF + n], W1[(size_t)(k + 1) * FF + n]));
        o.y = h2u(__floats2half2_rn(W1[(size_t)(k + 8) * FF + n], W1[(size_t)(k + 9) * FF + n]));
        g_Wt16[mode][hf][gid & 4095] = o;
    } else if (b >= 65 && b <= 96) {
        // prepW2: gate B pack
        const int gid = (b - 65) * 256 + tid;         // 0..8191
        const int lane = gid & 31, g = (gid >> 5) & 31, ks = gid >> 10;
        const int pl = lane >> 2, j = pl >> 1, fc = pl & 1;
        const int nt = g & 7, wn = g >> 3;
        const int n = wn * 32 + j * 8 + nt + fc * 128;
        const int k = HN + ks * 16 + (lane & 3) * 2;
        uint2 o;
        o.x = h2u(__floats2half2_rn(W1[(size_t)k * FF + n], W1[(size_t)(k + 1) * FF + n]));
        o.y = h2u(__floats2half2_rn(W1[(size_t)(k + 8) * FF + n], W1[(size_t)(k + 9) * FF + n]));
        g_Wt2[gid] = o;
    }
}

// A pack: 2 independent units per thread
__global__ void prepA_kernel(const float* __restrict__ A, uint4* __restrict__ dst,
                             int M, int nunits, int halfu) {
    const int gid0 = blockIdx.x * blockDim.x + threadIdx.x;
#pragma unroll
    for (int rep = 0; rep < 2; rep++) {
        const int gid = gid0 + rep * halfu;
        if (gid >= nunits) continue;
        const int lane = gid & 31, mt = (gid >> 5) & 3, ks = (gid >> 7) & 7;
        const int block = gid >> 10;
        const int r0 = block * 64 + mt * 16 + (lane >> 2);
        const int r1 = r0 + 8;
        const int c0 = ks * 16 + (lane & 3) * 2;
        float2 v00 = make_float2(0.f, 0.f), v01 = v00, v10 = v00, v11 = v00;
        if (r0 < M) {
            v00 = *(const float2*)(A + (size_t)r0 * HN + c0);
            v01 = *(const float2*)(A + (size_t)r0 * HN + c0 + 8);
        }
        if (r1 < M) {
            v10 = *(const float2*)(A + (size_t)r1 * HN + c0);
            v11 = *(const float2*)(A + (size_t)r1 * HN + c0 + 8);
        }
        uint4 o;
        o.x = h2u(__floats2half2_rn(v00.x, v00.y));
        o.y = h2u(__floats2half2_rn(v10.x, v10.y));
        o.z = h2u(__floats2half2_rn(v01.x, v01.y));
        o.w = h2u(__floats2half2_rn(v11.x, v11.y));
        dst[gid] = o;
    }
}

// ---------------- pass GEMMs (R16) ----------------
// MODE 0: g_P16 = node_emb @ W_top + b1
// MODE 1: BN1 column stats of (edge_emb @ W_bot + P16[i[row]])
template <int MODE>
__global__ __launch_bounds__(256, 2) void mma_gemm(
    const uint4* __restrict__ Apk, const float* __restrict__ b1,
    const void* __restrict__ ibuf, __half* __restrict__ outv, int M)
{
    extern __shared__ char smem[];
    uint2* Bs = (uint2*)smem;
    float* sstat = (float*)(smem + SSTAT_OFF);

    const int tid = threadIdx.x, lane = tid & 31, wid = tid >> 5;
    const int wm = wid & 1, wn = wid >> 1;
    const int ntiles = (M + 127) >> 7;
    const long long njobs = (long long)ntiles * 2;
    const int G = gridDim.x;
    const int halfc = blockIdx.x & 1;
    const int is64 = (MODE == 1) ? g_is64 : 0;

    const uint32_t wbuf = smem_u32(smem) + ABUF_OFF + (uint32_t)wid * 8192
                          + (uint32_t)lane * 16;
    {
        const uint4* src = (const uint4*)&g_Wt16[MODE][halfc][0];
        uint4* dstv = (uint4*)Bs;
        for (int i = tid; i < 2048; i += 256) dstv[i] = src[i];
    }
    if (MODE == 1) sstat[tid] = 0.f;
    __syncthreads();

    float acc[4][4][4];
#pragma unroll
    for (int mt = 0; mt < 4; mt++)
#pragma unroll
        for (int nt = 0; nt < 4; nt++)
#pragma unroll
            for (int r = 0; r < 4; r++) acc[mt][nt][r] = 0.f;

    float s[4][2], q[4][2];
    if (MODE == 1) {
#pragma unroll
        for (int nt = 0; nt < 4; nt++) {
            s[nt][0] = s[nt][1] = 0.f; q[nt][0] = q[nt][1] = 0.f;
        }
    }

    for (long long job = blockIdx.x; job < njobs; job += G) {
        const long long tile = job >> 1;
        const uint4* abase = Apk + ((tile * 2 + wm) << 10) + lane;

#pragma unroll
        for (int p = 0; p < DEPTH; p++) {
#pragma unroll
            for (int mt = 0; mt < 4; mt++)
                cpasync16(wbuf + (uint32_t)((p * 4 + mt) << 9),
                          abase + p * 128 + mt * 32);
            CP_COMMIT();
        }
#pragma unroll
        for (int ks = 0; ks < 8; ks++) {
            const int wn_ = (7 - ks < DEPTH - 1) ? (7 - ks) : (DEPTH - 1);
            cp_wait(wn_);
            uint2 bfr[4];
#pragma unroll
            for (int nt = 0; nt < 4; nt++)
                bfr[nt] = Bs[(ks * 16 + wn * 4 + nt) * 32 + lane];
            uint4 a[4];
#pragma unroll
            for (int mt = 0; mt < 4; mt++)
                lds128(a[mt], wbuf + (uint32_t)((((ks % DEPTH) * 4) + mt) << 9));
            if (ks + DEPTH < 8) {
#pragma unroll
                for (int mt = 0; mt < 4; mt++)
                    cpasync16(wbuf + (uint32_t)(((((ks + DEPTH) % DEPTH) * 4) + mt) << 9),
                              abase + (ks + DEPTH) * 128 + mt * 32);
                CP_COMMIT();
            }
#pragma unroll
            for (int mt = 0; mt < 4; mt++)
#pragma unroll
                for (int nt = 0; nt < 4; nt++)
                    mma16(acc[mt][nt], a[mt], bfr[nt]);
        }

        const long long rbase = tile << 7;
#pragma unroll
        for (int mt = 0; mt < 4; mt++) {
            long long pb[2]; bool valid[2]; long long rown[2];
#pragma unroll
            for (int h = 0; h < 2; h++) {
                const long long row = rbase + wm * 64 + mt * 16 + (lane >> 2) + h * 8;
                rown[h] = row;
                valid[h] = row < (long long)M;
                pb[h] = 0;
                if (MODE == 1 && valid[h]) {
                    const long long idx = is64 ? ((const long long*)ibuf)[row]
                                               : (long long)((const int*)ibuf)[row];
                    pb[h] = idx * FF;
                }
            }
#pragma unroll
            for (int nt = 0; nt < 4; nt++) {
                const int c0 = halfc * 128 + wn * 32 + nt * 8 + 2 * (lane & 3);
#pragma unroll
                for (int h = 0; h < 2; h++) {
                    if (!valid[h]) continue;
                    if (MODE == 0) {
                        const float2 add = *(const float2*)(b1 + c0);
                        *(__half2*)(outv + rown[h] * FF + c0) =
                            __floats2half2_rn(acc[mt][nt][2 * h] + add.x,
                                              acc[mt][nt][2 * h + 1] + add.y);
                    } else {
                        const float2 p = __half22float2(
                            *(const __half2*)(g_P16 + pb[h] + c0));
                        const float ox = acc[mt][nt][2 * h] + p.x;
                        const float oy = acc[mt][nt][2 * h + 1] + p.y;
                        s[nt][0] += ox; q[nt][0] = fmaf(ox, ox, q[nt][0]);
                        s[nt][1] += oy; q[nt][1] = fmaf(oy, oy, q[nt][1]);
                    }
                }
                acc[mt][nt][0] = 0.f; acc[mt][nt][1] = 0.f;
                acc[mt][nt][2] = 0.f; acc[mt][nt][3] = 0.f;
            }
        }
    }

    if (MODE == 1) {
#pragma unroll
        for (int o = 4; o < 32; o <<= 1) {
#pragma unroll
            for (int nt = 0; nt < 4; nt++) {
                s[nt][0] += __shfl_xor_sync(0xffffffffu, s[nt][0], o);
                s[nt][1] += __shfl_xor_sync(0xffffffffu, s[nt][1], o);
                q[nt][0] += __shfl_xor_sync(0xffffffffu, q[nt][0], o);
                q[nt][1] += __shfl_xor_sync(0xffffffffu, q[nt][1], o);
            }
        }
        if (lane < 4) {
#pragma unroll
            for (int nt = 0; nt < 4; nt++) {
                const int lc = wn * 32 + nt * 8 + 2 * lane;
                atomicAdd(&sstat[lc], s[nt][0]);
                atomicAdd(&sstat[lc + 1], s[nt][1]);
                atomicAdd(&sstat[128 + lc], q[nt][0]);
                atomicAdd(&sstat[128 + lc + 1], q[nt][1]);
            }
        }
        __syncthreads();
        if (tid < 128) {
            atomicAdd(&g_stats1[halfc * 128 + tid], sstat[tid]);
            atomicAdd(&g_stats1[256 + halfc * 128 + tid], sstat[128 + tid]);
        }
    }
}

// ---------------- pass2: GEMM + gate + scatter (inline finalize) ------------
__global__ __launch_bounds__(256, 2) void gemm_gate(
    const uint4* __restrict__ Apk, const void* __restrict__ ibuf,
    const float* __restrict__ gamma1, const float* __restrict__ beta1,
    float invE, int E)
{
    extern __shared__ char smem[];
    uint2* B2s = (uint2*)smem;
    float* ss = (float*)(smem + SS_OFF);

    const int tid = threadIdx.x, lane = tid & 31, wid = tid >> 5;
    const int wm = wid & 1, wn = wid >> 1;
    const int nblk = (E + 63) >> 6;
    const int G = gridDim.x;
    const int is64 = g_is64;

    {
        const uint4* src = (const uint4*)&g_Wt2[0];
        uint4* dstv = (uint4*)B2s;
        for (int i = tid; i < 4096; i += 256) dstv[i] = src[i];
    }
    {   // inline BN1 finalize (per-CTA, trivial)
        const float mu  = g_stats1[tid] * invE;
        const float var = g_stats1[FF + tid] * invE - mu * mu;
        const float sc  = gamma1[tid] * rsqrtf(var + EPS);
        ss[tid] = sc;
        ss[256 + tid] = beta1[tid] - mu * sc;
    }
    __syncthreads();

    const uint32_t wbuf = smem_u32(smem) + RING_OFF + (uint32_t)wid * 4096
                          + (uint32_t)lane * 16;
    const int kbase = wn * 32 + (lane & 3) * 8;

    float acc[2][8][4];
#pragma unroll
    for (int mt = 0; mt < 2; mt++)
#pragma unroll
        for (int nt = 0; nt < 8; nt++)
#pragma unroll
            for (int r = 0; r < 4; r++) acc[mt][nt][r] = 0.f;

    for (int job = blockIdx.x; job < nblk; job += G) {
        const uint4* abase = Apk + ((long long)job << 10) + lane;

#pragma unroll
        for (int p = 0; p < DEPTH; p++) {
#pragma unroll
            for (int mt = 0; mt < 2; mt++)
                cpasync16(wbuf + (uint32_t)((p * 2 + mt) << 9),
                          abase + (p * 4 + wm * 2 + mt) * 32);
            CP_COMMIT();
        }
#pragma unroll
        for (int ks = 0; ks < 8; ks++) {
            const int wn_ = (7 - ks < DEPTH - 1) ? (7 - ks) : (DEPTH - 1);
            cp_wait(wn_);
            uint2 bfr[8];
#pragma unroll
            for (int nt = 0; nt < 8; nt++)
                bfr[nt] = B2s[(ks * 32 + wn * 8 + nt) * 32 + lane];
            uint4 a[2];
#pragma unroll
            for (int mt = 0; mt < 2; mt++)
                lds128(a[mt], wbuf + (uint32_t)((((ks % DEPTH) * 2) + mt) << 9));
            if (ks + DEPTH < 8) {
#pragma unroll
                for (int mt = 0; mt < 2; mt++)
                    cpasync16(wbuf + (uint32_t)(((((ks + DEPTH) % DEPTH) * 2) + mt) << 9),
                              abase + ((ks + DEPTH) * 4 + wm * 2 + mt) * 32);
                CP_COMMIT();
            }
#pragma unroll
            for (int mt = 0; mt < 2; mt++)
#pragma unroll
                for (int nt = 0; nt < 8; nt++)
                    mma16(acc[mt][nt], a[mt], bfr[nt]);
        }

#pragma unroll
        for (int mt = 0; mt < 2; mt++) {
#pragma unroll
            for (int h = 0; h < 2; h++) {
                const long long row = (long long)job * 64 + wm * 32 + mt * 16
                                      + (lane >> 2) + h * 8;
                if (row < (long long)E) {
                    const long long idx = is64 ? ((const long long*)ibuf)[row]
                                               : (long long)((const int*)ibuf)[row];
                    const __half* prow = g_P16 + idx * FF;
                    const uint4 pfv = *(const uint4*)(prow + kbase);
                    const uint4 pcv = *(const uint4*)(prow + 128 + kbase);
                    float pf[8], pc[8];
#pragma unroll
                    for (int p2 = 0; p2 < 4; p2++) {
                        const float2 f2 = __half22float2(*(((const __half2*)&pfv) + p2));
                        const float2 c2 = __half22float2(*(((const __half2*)&pcv) + p2));
                        pf[2 * p2] = f2.x; pf[2 * p2 + 1] = f2.y;
                        pc[2 * p2] = c2.x; pc[2 * p2 + 1] = c2.y;
                    }
                    float m[8];
#pragma unroll
                    for (int nt = 0; nt < 8; nt++) {
                        const int k = kbase + nt;
                        const float hF = acc[mt][nt][2 * h] + pf[nt];
                        const float hC = acc[mt][nt][2 * h + 1] + pc[nt];
                        m[nt] = sigmoida(hF * ss[k] + ss[256 + k])
                              * tanha(hC * ss[128 + k] + ss[384 + k]);
                    }
                    float* dst = g_agg + idx * HN + kbase;
                    asm volatile("red.global.add.v4.f32 [%0], {%1, %2, %3, %4};"
                                 :: "l"(dst), "f"(m[0]), "f"(m[1]), "f"(m[2]), "f"(m[3]) : "memory");
                    asm volatile("red.global.add.v4.f32 [%0], {%1, %2, %3, %4};"
                                 :: "l"(dst + 4), "f"(m[4]), "f"(m[5]), "f"(m[6]), "f"(m[7]) : "memory");
                }
            }
#pragma unroll
            for (int nt = 0; nt < 8; nt++) {
                acc[mt][nt][0] = 0.f; acc[mt][nt][1] = 0.f;
                acc[mt][nt][2] = 0.f; acc[mt][nt][3] = 0.f;
            }
        }
    }
}

// ---------------- BN2 + final ----------------
__global__ void stats2_kernel(int N) {
    const int t = blockIdx.x * blockDim.x + threadIdx.x;
    const int col = t & (HN - 1);
    const int r0 = t >> 7;
    const int rs = (gridDim.x * blockDim.x) >> 7;
    float s = 0.f, sq = 0.f;
    for (long long r = r0; r < N; r += rs) {
        const float v = g_agg[r * HN + col];
        s += v; sq = fmaf(v, v, sq);
    }
    atomicAdd(&g_stats2[col], s);
    atomicAdd(&g_stats2[HN + col], sq);
}

__global__ void final_kernel(const float* __restrict__ node_emb,
                             const float* __restrict__ gamma2,
                             const float* __restrict__ beta2,
                             float* __restrict__ out, int total, float invN) {
    const int t = blockIdx.x * blockDim.x + threadIdx.x;
    if (t >= total) return;
    const int col = t & (HN - 1);
    const float mu  = g_stats2[col] * invN;
    const float var = g_stats2[HN + col] * invN - mu * mu;
    const float c1  = (g_agg[t] - mu) * rsqrtf(var + EPS) * gamma2[col] + beta2[col];
    out[t] = tanhf_(node_emb[t] + c1);
}

// ---------------- launch ----------------
extern "C" void kernel_launch(void* const* d_in, const int* in_sizes, int n_in,
                              void* d_out, int out_size) {
    const float* node_emb = (const float*)d_in[0];
    const float* edge_emb = (const float*)d_in[1];
    const void*  ibuf     = d_in[2];
    const float* W1       = (const float*)d_in[3];
    const float* b1       = (const float*)d_in[4];
    const float* gamma1   = (const float*)d_in[5];
    const float* beta1    = (const float*)d_in[6];
    const float* gamma2   = (const float*)d_in[7];
    const float* beta2    = (const float*)d_in[8];
    float* out = (float*)d_out;

    const int N = in_sizes[0] / HN;
    const int E = in_sizes[1] / HN;

    static bool init_done = false;
    static cudaStream_t s1;
    static cudaEvent_t e0, e1;
    if (!init_done) {
        cudaFuncSetAttribute(mma_gemm<0>, cudaFuncAttributeMaxDynamicSharedMemorySize, SMEM_SZ);
        cudaFuncSetAttribute(mma_gemm<1>, cudaFuncAttributeMaxDynamicSharedMemorySize, SMEM_SZ);
        cudaFuncSetAttribute(gemm_gate, cudaFuncAttributeMaxDynamicSharedMemorySize, SMEM2_SZ);
        cudaStreamCreateWithFlags(&s1, cudaStreamNonBlocking);
        cudaEventCreateWithFlags(&e0, cudaEventDisableTiming);
        cudaEventCreateWithFlags(&e1, cudaEventDisableTiming);
        init_done = true;
    }

    __half* g_P_ptr;  cudaGetSymbolAddress((void**)&g_P_ptr, g_P16);
    uint4*  g_Ae_ptr; cudaGetSymbolAddress((void**)&g_Ae_ptr, g_Ae);
    uint4*  g_An_ptr; cudaGetSymbolAddress((void**)&g_An_ptr, g_An);

    const int unitsN = NBLK_N * 1024;
    const int unitsE = NBLK_E * 1024;
    const int halfN = (unitsN + 1) / 2;
    const int halfE = (unitsE + 1) / 2;

    // ---- fork: edge A pack on side stream (independent of node chain) ----
    cudaEventRecord(e0, 0);
    cudaStreamWaitEvent(s1, e0, 0);
    prepA_kernel<<<(halfE + 255) / 256, 256, 0, s1>>>(edge_emb, g_Ae_ptr, E, unitsE, halfE);
    cudaEventRecord(e1, s1);

    // ---- node chain + setup on main stream ----
    setup_kernel<<<2048, 256>>>((const unsigned*)ibuf, W1, N * HN);
    prepA_kernel<<<(halfN + 255) / 256, 256>>>(node_emb, g_An_ptr, N, unitsN, halfN);
    mma_gemm<0><<<296, 256, SMEM_SZ>>>(g_An_ptr, b1, ibuf, g_P_ptr, N);

    // ---- join, then stats pass / gate / BN2 ----
    cudaStreamWaitEvent(0, e1, 0);
    mma_gemm<1><<<296, 256, SMEM_SZ>>>(g_Ae_ptr, b1, ibuf, nullptr, E);
    gemm_gate<<<296, 256, SMEM2_SZ>>>(g_Ae_ptr, ibuf, gamma1, beta1,
                                      1.0f / (float)E, E);
    stats2_kernel<<<1024, 256>>>(N);
    final_kernel<<<(N * HN + 255) / 256, 256>>>(node_emb, gamma2, beta2, out,
                                                N * HN, 1.0f / (float)N);
}